// round 1
// baseline (speedup 1.0000x reference)
#include <cuda_runtime.h>
#include <cstdint>
#include <math.h>

// ---------------- problem constants (from setup_inputs) ----------------
#define BB   4
#define NQ   8000
#define CC   256
#define NHD  8
#define NLV  4
#define NPT  4
#define DH   32
#define S_TOT 19947

__device__ __constant__ int c_lh[NLV]    = {100, 50, 25, 13};
__device__ __constant__ int c_lw[NLV]    = {150, 75, 38, 19};
__device__ __constant__ int c_lst[NLV]   = {0, 15000, 18750, 19700};

// ---------------- scratch (static device allocations are allowed) ------
__device__ float g_value[(size_t)BB * S_TOT * CC];   // [B,S,NH,DH]
__device__ float g_off  [(size_t)BB * NQ * CC];      // [B,Nq,256]
__device__ float g_attn [(size_t)BB * NQ * 128];     // [B,Nq,128] logits
__device__ float g_smp  [(size_t)BB * NQ * CC];      // [B,Nq,NH,DH]

// ---------------- GEMM: C[M,N] = A[M,K] * W[N,K]^T + bias[N] -----------
// 128x128 tile, BK=8, 256 threads, 8x8 per thread. K=256, N multiple of 128.
__global__ void __launch_bounds__(256) gemm_nt_kernel(
    const float* __restrict__ A, const float* __restrict__ W,
    const float* __restrict__ bias, float* __restrict__ Cmat,
    int M, int N, int K)
{
    __shared__ float As[8][128];
    __shared__ float Ws[8][128];
    const int tid = threadIdx.x;
    const int bm = blockIdx.y * 128;
    const int bn = blockIdx.x * 128;
    const int tx = tid & 15;        // N-dir
    const int ty = tid >> 4;        // M-dir
    const int lm = tid >> 1;        // 0..127 load row
    const int lk = (tid & 1) * 4;   // 0 or 4

    float acc[8][8];
#pragma unroll
    for (int i = 0; i < 8; i++)
#pragma unroll
        for (int j = 0; j < 8; j++) acc[i][j] = 0.f;

    const bool a_ok = (bm + lm) < M;
    const float* Aptr = A + (size_t)(bm + lm) * K + lk;
    const float* Wptr = W + (size_t)(bn + lm) * K + lk;

    for (int k0 = 0; k0 < K; k0 += 8) {
        float4 av = a_ok ? *(const float4*)(Aptr + k0) : make_float4(0.f, 0.f, 0.f, 0.f);
        float4 wv = *(const float4*)(Wptr + k0);
        As[lk + 0][lm] = av.x; As[lk + 1][lm] = av.y;
        As[lk + 2][lm] = av.z; As[lk + 3][lm] = av.w;
        Ws[lk + 0][lm] = wv.x; Ws[lk + 1][lm] = wv.y;
        Ws[lk + 2][lm] = wv.z; Ws[lk + 3][lm] = wv.w;
        __syncthreads();
#pragma unroll
        for (int k = 0; k < 8; k++) {
            float4 a0 = *(const float4*)&As[k][ty * 8];
            float4 a1 = *(const float4*)&As[k][ty * 8 + 4];
            float4 b0 = *(const float4*)&Ws[k][tx * 8];
            float4 b1 = *(const float4*)&Ws[k][tx * 8 + 4];
            float a[8] = {a0.x, a0.y, a0.z, a0.w, a1.x, a1.y, a1.z, a1.w};
            float b[8] = {b0.x, b0.y, b0.z, b0.w, b1.x, b1.y, b1.z, b1.w};
#pragma unroll
            for (int i = 0; i < 8; i++)
#pragma unroll
                for (int j = 0; j < 8; j++) acc[i][j] += a[i] * b[j];
        }
        __syncthreads();
    }

#pragma unroll
    for (int i = 0; i < 8; i++) {
        int gm = bm + ty * 8 + i;
        if (gm < M) {
#pragma unroll
            for (int j = 0; j < 8; j++) {
                int gn = bn + tx * 8 + j;
                Cmat[(size_t)gm * N + gn] = acc[i][j] + bias[gn];
            }
        }
    }
}

// ---------------- sampling: softmax + bilinear gather ------------------
// one warp per (b, q, h); lane = channel (DH == 32).
__global__ void __launch_bounds__(256) sample_kernel(
    const float* __restrict__ ref)   // [B,NQ,NL,2]
{
    const int warp = (blockIdx.x * blockDim.x + threadIdx.x) >> 5;
    const int lane = threadIdx.x & 31;
    if (warp >= BB * NQ * NHD) return;

    const int h  = warp % NHD;
    const int bq = warp / NHD;      // b*NQ + q
    const int b  = bq / NQ;

    // --- softmax over 16 logits (lane-redundant, broadcast loads) ---
    const float* logit = g_attn + (size_t)bq * 128 + h * 16;
    float e[16];
    float m = -1e30f;
#pragma unroll
    for (int i = 0; i < 16; i++) { e[i] = logit[i]; m = fmaxf(m, e[i]); }
    float s = 0.f;
#pragma unroll
    for (int i = 0; i < 16; i++) { e[i] = __expf(e[i] - m); s += e[i]; }
    const float inv = 1.f / s;

    const float* offp = g_off + (size_t)bq * CC + h * (NLV * NPT * 2);

    float acc = 0.f;
#pragma unroll
    for (int l = 0; l < NLV; l++) {
        const float rx = ref[((size_t)bq * NLV + l) * 2 + 0];
        const float ry = ref[((size_t)bq * NLV + l) * 2 + 1];
        const int H = c_lh[l], W = c_lw[l];
        const float fW = (float)W, fH = (float)H;
        const float* vbase = g_value
            + ((size_t)(b * S_TOT + c_lst[l]) * NHD + h) * DH + lane;
#pragma unroll
        for (int p = 0; p < NPT; p++) {
            const float ox = offp[l * (NPT * 2) + p * 2 + 0];
            const float oy = offp[l * (NPT * 2) + p * 2 + 1];
            const float aw = e[l * NPT + p] * inv;
            // mirror reference op order: loc = ref + off/norm ; x = loc*W - 0.5
            const float x = (rx + ox / fW) * fW - 0.5f;
            const float y = (ry + oy / fH) * fH - 0.5f;
            const float x0f = floorf(x), y0f = floorf(y);
            const int ix0 = (int)x0f, iy0 = (int)y0f;
            const float wx1 = x - x0f, wy1 = y - y0f;
            const float wx0 = 1.f - wx1, wy0 = 1.f - wy1;

            float v = 0.f;
            {
                const int ix = ix0, iy = iy0;
                if (ix >= 0 && ix < W && iy >= 0 && iy < H)
                    v += (wx0 * wy0) * __ldg(vbase + (size_t)(iy * W + ix) * (NHD * DH));
            }
            {
                const int ix = ix0 + 1, iy = iy0;
                if (ix >= 0 && ix < W && iy >= 0 && iy < H)
                    v += (wx1 * wy0) * __ldg(vbase + (size_t)(iy * W + ix) * (NHD * DH));
            }
            {
                const int ix = ix0, iy = iy0 + 1;
                if (ix >= 0 && ix < W && iy >= 0 && iy < H)
                    v += (wx0 * wy1) * __ldg(vbase + (size_t)(iy * W + ix) * (NHD * DH));
            }
            {
                const int ix = ix0 + 1, iy = iy0 + 1;
                if (ix >= 0 && ix < W && iy >= 0 && iy < H)
                    v += (wx1 * wy1) * __ldg(vbase + (size_t)(iy * W + ix) * (NHD * DH));
            }
            acc += aw * v;
        }
    }
    g_smp[(size_t)(bq * NHD + h) * DH + lane] = acc;
}

// ---------------- launch ----------------
extern "C" void kernel_launch(void* const* d_in, const int* in_sizes, int n_in,
                              void* d_out, int out_size)
{
    (void)in_sizes; (void)n_in; (void)out_size;
    const float* query  = (const float*)d_in[0];
    const float* vlv    = (const float*)d_in[1];
    const float* refpts = (const float*)d_in[2];
    // d_in[3] = spatial_shapes (compile-time constants)
    const float* W_off  = (const float*)d_in[4];
    const float* b_off  = (const float*)d_in[5];
    const float* W_attn = (const float*)d_in[6];
    const float* b_attn = (const float*)d_in[7];
    const float* W_val  = (const float*)d_in[8];
    const float* b_val  = (const float*)d_in[9];
    const float* W_out  = (const float*)d_in[10];
    const float* b_out  = (const float*)d_in[11];
    float* out = (float*)d_out;

    float *p_value, *p_off, *p_attn, *p_smp;
    cudaGetSymbolAddress((void**)&p_value, g_value);
    cudaGetSymbolAddress((void**)&p_off,   g_off);
    cudaGetSymbolAddress((void**)&p_attn,  g_attn);
    cudaGetSymbolAddress((void**)&p_smp,   g_smp);

    const int Mv = BB * S_TOT;   // 79788
    const int Mq = BB * NQ;      // 32000

    // value projection: [B*S,256] @ W_val^T
    {
        dim3 grid(CC / 128, (Mv + 127) / 128);
        gemm_nt_kernel<<<grid, 256>>>(vlv, W_val, b_val, p_value, Mv, CC, CC);
    }
    // offset projection
    {
        dim3 grid(CC / 128, (Mq + 127) / 128);
        gemm_nt_kernel<<<grid, 256>>>(query, W_off, b_off, p_off, Mq, CC, CC);
    }
    // attention logits
    {
        dim3 grid(128 / 128, (Mq + 127) / 128);
        gemm_nt_kernel<<<grid, 256>>>(query, W_attn, b_attn, p_attn, Mq, 128, CC);
    }
    // softmax + bilinear sampling
    {
        const int nwarp = BB * NQ * NHD;            // 256000
        const int blocks = (nwarp * 32 + 255) / 256;
        sample_kernel<<<blocks, 256>>>(refpts);
    }
    // output projection -> d_out
    {
        dim3 grid(CC / 128, (Mq + 127) / 128);
        gemm_nt_kernel<<<grid, 256>>>(p_smp, W_out, b_out, out, Mq, CC, CC);
    }
}

// round 3
// speedup vs baseline: 1.4560x; 1.4560x over previous
#include <cuda_runtime.h>
#include <cuda_bf16.h>
#include <cstdint>
#include <math.h>

// ---------------- problem constants ----------------
#define BB   4
#define NQ   8000
#define CC   256
#define NHD  8
#define NLV  4
#define NPT  4
#define DH   32
#define S_TOT 19947

// ---------------- scratch ----------------
__device__ float g_value[(size_t)BB * S_TOT * CC];   // [B,S,NH,DH]
__device__ float g_off  [(size_t)BB * NQ * CC];      // [B,Nq,256]
__device__ float g_attn [(size_t)BB * NQ * 128];     // [B,Nq,128] logits
__device__ float g_smp  [(size_t)BB * NQ * CC];      // [B,Nq,NH,DH]

// ---------------- helpers ----------------
__device__ __forceinline__ uint32_t smem_u32(const void* p) {
    uint32_t a;
    asm("{ .reg .u64 t; cvta.to.shared.u64 t, %1; cvt.u32.u64 %0, t; }" : "=r"(a) : "l"(p));
    return a;
}
__device__ __forceinline__ void ldsm4(uint32_t* r, uint32_t addr) {
    asm volatile("ldmatrix.sync.aligned.m8n8.x4.shared.b16 {%0,%1,%2,%3}, [%4];"
        : "=r"(r[0]), "=r"(r[1]), "=r"(r[2]), "=r"(r[3]) : "r"(addr));
}
__device__ __forceinline__ void mma_bf16(float* c, const uint32_t* a, const uint32_t* b) {
    asm volatile(
        "mma.sync.aligned.m16n8k16.row.col.f32.bf16.bf16.f32 "
        "{%0,%1,%2,%3}, {%4,%5,%6,%7}, {%8,%9}, {%0,%1,%2,%3};"
        : "+f"(c[0]), "+f"(c[1]), "+f"(c[2]), "+f"(c[3])
        : "r"(a[0]), "r"(a[1]), "r"(a[2]), "r"(a[3]), "r"(b[0]), "r"(b[1]));
}
__device__ __forceinline__ uint32_t pack_split(float v, uint32_t& lo_out_partial, int sel) {
    return 0; // unused
}

// ============ HMMA GEMM:  C[M,N] = A[M,256] @ W[N,256]^T + bias ============
// split-bf16 (hi+lo), 3 MMA terms. Block 128x128, K staged 4 x 64.
// smem planes (swizzled, 128B rows of 64 bf16):
//   [0,16K) A_hi  [16K,32K) A_lo  [32K,48K) B_hi  [48K,64K) B_lo  [64K,+512) bias
__global__ void __launch_bounds__(256) gemm_tc_kernel(
    const float* __restrict__ A, const float* __restrict__ Wm,
    const float* __restrict__ bias, float* __restrict__ Cmat,
    int M, int N)
{
    extern __shared__ char smraw[];
    char* sm = (char*)(((uintptr_t)smraw + 1023) & ~(uintptr_t)1023);
    const uint32_t su = smem_u32(sm);
    float* pbias = (float*)(sm + 65536);

    const int tid  = threadIdx.x;
    const int lane = tid & 31;
    const int warp = tid >> 5;
    const int wm = (warp >> 2) * 64;
    const int wn = (warp & 3) * 32;
    const int bm = blockIdx.y * 128;
    const int bn = blockIdx.x * 128;

    if (tid < 128) pbias[tid] = bias[bn + tid];

    float acc[4][4][4];
#pragma unroll
    for (int i = 0; i < 4; i++)
#pragma unroll
        for (int j = 0; j < 4; j++)
#pragma unroll
            for (int k = 0; k < 4; k++) acc[i][j][k] = 0.f;

    // ldmatrix lane addressing (byte offsets in plane; swizzle xor mask)
    const uint32_t mx = (uint32_t)((lane & 7) << 4);
    uint32_t aRow[4], bRow[2];
#pragma unroll
    for (int mi = 0; mi < 4; mi++)
        aRow[mi] = (uint32_t)((wm + mi * 16 + (lane & 15)) * 128);
    const uint32_t colA = (uint32_t)((lane >> 4) * 16);
#pragma unroll
    for (int nj2 = 0; nj2 < 2; nj2++)
        bRow[nj2] = (uint32_t)((wn + nj2 * 16 + (lane & 7) + ((lane >> 4) & 1) * 8) * 128);
    const uint32_t colB = (uint32_t)(((lane >> 3) & 1) * 16);

    for (int s = 0; s < 4; s++) {
        const int ks = s * 64;
        // ---- A tile 128x64 -> bf16 hi/lo planes ----
#pragma unroll 4
        for (int i = tid; i < 4096; i += 256) {
            const int r = i >> 5, cp = i & 31;
            const int grow = bm + r;
            float2 v = (grow < M) ? *(const float2*)(A + (size_t)grow * 256 + ks + cp * 2)
                                  : make_float2(0.f, 0.f);
            __nv_bfloat16 h0 = __float2bfloat16(v.x);
            __nv_bfloat16 h1 = __float2bfloat16(v.y);
            __nv_bfloat16 l0 = __float2bfloat16(v.x - __bfloat162float(h0));
            __nv_bfloat16 l1 = __float2bfloat16(v.y - __bfloat162float(h1));
            uint32_t hp = (uint32_t)__bfloat16_as_ushort(h0) | ((uint32_t)__bfloat16_as_ushort(h1) << 16);
            uint32_t lp = (uint32_t)__bfloat16_as_ushort(l0) | ((uint32_t)__bfloat16_as_ushort(l1) << 16);
            const uint32_t off = (uint32_t)(r * 128) + (uint32_t)((cp * 4) ^ ((r & 7) << 4));
            *(uint32_t*)(sm + off)         = hp;
            *(uint32_t*)(sm + 16384 + off) = lp;
        }
        // ---- B tile 128x64 (always valid rows) ----
#pragma unroll 4
        for (int i = tid; i < 4096; i += 256) {
            const int r = i >> 5, cp = i & 31;
            float2 v = *(const float2*)(Wm + (size_t)(bn + r) * 256 + ks + cp * 2);
            __nv_bfloat16 h0 = __float2bfloat16(v.x);
            __nv_bfloat16 h1 = __float2bfloat16(v.y);
            __nv_bfloat16 l0 = __float2bfloat16(v.x - __bfloat162float(h0));
            __nv_bfloat16 l1 = __float2bfloat16(v.y - __bfloat162float(h1));
            uint32_t hp = (uint32_t)__bfloat16_as_ushort(h0) | ((uint32_t)__bfloat16_as_ushort(h1) << 16);
            uint32_t lp = (uint32_t)__bfloat16_as_ushort(l0) | ((uint32_t)__bfloat16_as_ushort(l1) << 16);
            const uint32_t off = (uint32_t)(r * 128) + (uint32_t)((cp * 4) ^ ((r & 7) << 4));
            *(uint32_t*)(sm + 32768 + off) = hp;
            *(uint32_t*)(sm + 49152 + off) = lp;
        }
        __syncthreads();

#pragma unroll
        for (int kk = 0; kk < 4; kk++) {
            uint32_t ah[4][4], al[4][4], bh[2][4], bl[2][4];
            const uint32_t ca = ((uint32_t)(kk * 32) + colA) ^ mx;
            const uint32_t cb = ((uint32_t)(kk * 32) + colB) ^ mx;
#pragma unroll
            for (int mi = 0; mi < 4; mi++) {
                const uint32_t ad = su + aRow[mi] + ca;
                ldsm4(ah[mi], ad);
                ldsm4(al[mi], ad + 16384);
            }
#pragma unroll
            for (int nj2 = 0; nj2 < 2; nj2++) {
                const uint32_t bd = su + 32768 + bRow[nj2] + cb;
                ldsm4(bh[nj2], bd);
                ldsm4(bl[nj2], bd + 16384);
            }
#pragma unroll
            for (int mi = 0; mi < 4; mi++) {
#pragma unroll
                for (int nj = 0; nj < 4; nj++) {
                    const uint32_t* bfh = &bh[nj >> 1][(nj & 1) * 2];
                    const uint32_t* bfl = &bl[nj >> 1][(nj & 1) * 2];
                    mma_bf16(acc[mi][nj], ah[mi], bfh);
                    mma_bf16(acc[mi][nj], ah[mi], bfl);
                    mma_bf16(acc[mi][nj], al[mi], bfh);
                }
            }
        }
        __syncthreads();
    }

    // ---- epilogue ----
    const int r0 = lane >> 2;
    const int c0 = (lane & 3) * 2;
#pragma unroll
    for (int mi = 0; mi < 4; mi++) {
        const int gm = bm + wm + mi * 16 + r0;
#pragma unroll
        for (int half = 0; half < 2; half++) {
            const int gmr = gm + half * 8;
            if (gmr < M) {
                float* op = Cmat + (size_t)gmr * N + bn;
#pragma unroll
                for (int nj = 0; nj < 4; nj++) {
                    const int cl = wn + nj * 8 + c0;
                    float2 o;
                    o.x = acc[mi][nj][half * 2 + 0] + pbias[cl];
                    o.y = acc[mi][nj][half * 2 + 1] + pbias[cl + 1];
                    *(float2*)(op + cl) = o;
                }
            }
        }
    }
}

// ---------------- sampling: warp-cooperative softmax + bilinear gather --
// one warp per (b,q,h). lanes 0..15 own one (level,point) sample;
// gather phase: lane = channel.
__global__ void __launch_bounds__(256) sample_kernel(
    const float* __restrict__ ref)   // [B,NQ,NL,2]
{
    constexpr int LH[4]  = {100, 50, 25, 13};
    constexpr int LW[4]  = {150, 75, 38, 19};
    constexpr int LST[4] = {0, 15000, 18750, 19700};

    const int warp = (blockIdx.x * blockDim.x + threadIdx.x) >> 5;
    const int lane = threadIdx.x & 31;
    if (warp >= BB * NQ * NHD) return;

    const int h  = warp % NHD;
    const int bq = warp / NHD;
    const int b  = bq / NQ;

    const int sl = (lane >> 2) & 3;   // this lane's sample level

    // softmax over 16 logits, one per lane
    const float* logit = g_attn + (size_t)bq * 128 + h * 16;
    float lg = (lane < 16) ? logit[lane] : -1e30f;
    float mxv = lg;
#pragma unroll
    for (int o = 8; o; o >>= 1) mxv = fmaxf(mxv, __shfl_xor_sync(0xffffffffu, mxv, o, 16));
    float ev = __expf(lg - mxv);
    float sum = ev;
#pragma unroll
    for (int o = 8; o; o >>= 1) sum += __shfl_xor_sync(0xffffffffu, sum, o, 16);
    const float aw = ev / sum;

    // per-lane sample coords
    const float2 off2 = ((const float2*)(g_off + (size_t)bq * 256 + h * 32))[lane & 15];
    const float2 rxy  = ((const float2*)(ref + (size_t)bq * 8))[sl];
    const float fW = (float)LW[sl], fH = (float)LH[sl];
    const float x = (rxy.x + off2.x / fW) * fW - 0.5f;
    const float y = (rxy.y + off2.y / fH) * fH - 0.5f;
    const float x0f = floorf(x), y0f = floorf(y);
    const int ix0 = (int)x0f, iy0 = (int)y0f;
    const float wx1 = x - x0f, wy1 = y - y0f;

    float accv = 0.f;
#pragma unroll
    for (int l = 0; l < 4; l++) {
        const int W = LW[l], H = LH[l];
        const float* vbase = g_value
            + ((size_t)(b * S_TOT + LST[l]) * NHD + h) * DH + lane;
#pragma unroll
        for (int p = 0; p < 4; p++) {
            const int s = l * 4 + p;
            const int   bix = __shfl_sync(0xffffffffu, ix0, s);
            const int   biy = __shfl_sync(0xffffffffu, iy0, s);
            const float bwx = __shfl_sync(0xffffffffu, wx1, s);
            const float bwy = __shfl_sync(0xffffffffu, wy1, s);
            const float baw = __shfl_sync(0xffffffffu, aw,  s);
            const float wx0 = 1.f - bwx, wy0 = 1.f - bwy;
            const bool xi0 = (bix >= 0) && (bix < W);
            const bool xi1 = (bix + 1 >= 0) && (bix + 1 < W);
            const bool yi0 = (biy >= 0) && (biy < H);
            const bool yi1 = (biy + 1 >= 0) && (biy + 1 < H);
            float v = 0.f;
            const float* rp0 = vbase + (ptrdiff_t)(biy * W) * 256;
            if (yi0) {
                if (xi0) v += (wx0 * wy0) * __ldg(rp0 + (ptrdiff_t)bix * 256);
                if (xi1) v += (bwx * wy0) * __ldg(rp0 + (ptrdiff_t)(bix + 1) * 256);
            }
            if (yi1) {
                const float* rp1 = rp0 + (ptrdiff_t)W * 256;
                if (xi0) v += (wx0 * bwy) * __ldg(rp1 + (ptrdiff_t)bix * 256);
                if (xi1) v += (bwx * bwy) * __ldg(rp1 + (ptrdiff_t)(bix + 1) * 256);
            }
            accv += baw * v;
        }
    }
    g_smp[(size_t)(bq * NHD + h) * DH + lane] = accv;
}

// ---------------- launch ----------------
#define GEMM_SMEM_BYTES 67072

extern "C" void kernel_launch(void* const* d_in, const int* in_sizes, int n_in,
                              void* d_out, int out_size)
{
    (void)in_sizes; (void)n_in; (void)out_size;
    const float* query  = (const float*)d_in[0];
    const float* vlv    = (const float*)d_in[1];
    const float* refpts = (const float*)d_in[2];
    const float* W_off  = (const float*)d_in[4];
    const float* b_off  = (const float*)d_in[5];
    const float* W_attn = (const float*)d_in[6];
    const float* b_attn = (const float*)d_in[7];
    const float* W_val  = (const float*)d_in[8];
    const float* b_val  = (const float*)d_in[9];
    const float* W_out  = (const float*)d_in[10];
    const float* b_out  = (const float*)d_in[11];
    float* out = (float*)d_out;

    cudaFuncSetAttribute(gemm_tc_kernel,
                         cudaFuncAttributeMaxDynamicSharedMemorySize, GEMM_SMEM_BYTES);

    float *p_value, *p_off, *p_attn, *p_smp;
    cudaGetSymbolAddress((void**)&p_value, g_value);
    cudaGetSymbolAddress((void**)&p_off,   g_off);
    cudaGetSymbolAddress((void**)&p_attn,  g_attn);
    cudaGetSymbolAddress((void**)&p_smp,   g_smp);

    const int Mv = BB * S_TOT;   // 79788
    const int Mq = BB * NQ;      // 32000

    { dim3 g(2, (Mv + 127) / 128); gemm_tc_kernel<<<g, 256, GEMM_SMEM_BYTES>>>(vlv,   W_val,  b_val,  p_value, Mv, 256); }
    { dim3 g(2, (Mq + 127) / 128); gemm_tc_kernel<<<g, 256, GEMM_SMEM_BYTES>>>(query, W_off,  b_off,  p_off,   Mq, 256); }
    { dim3 g(1, (Mq + 127) / 128); gemm_tc_kernel<<<g, 256, GEMM_SMEM_BYTES>>>(query, W_attn, b_attn, p_attn,  Mq, 128); }
    {
        const int nwarp = BB * NQ * NHD;
        const int blocks = (nwarp * 32 + 255) / 256;
        sample_kernel<<<blocks, 256>>>(refpts);
    }
    { dim3 g(2, (Mq + 127) / 128); gemm_tc_kernel<<<g, 256, GEMM_SMEM_BYTES>>>(p_smp, W_out,  b_out,  out,     Mq, 256); }
}

// round 4
// speedup vs baseline: 2.3550x; 1.6174x over previous
#include <cuda_runtime.h>
#include <cuda_bf16.h>
#include <cstdint>
#include <math.h>

// ---------------- problem constants ----------------
#define BB   4
#define NQ   8000
#define CC   256
#define NHD  8
#define NLV  4
#define NPT  4
#define DH   32
#define S_TOT 19947

#define MV (BB * S_TOT)   // 79788
#define MQ (BB * NQ)      // 32000

// ---------------- scratch ----------------
__device__ float g_value[(size_t)MV * CC];           // [B,S,NH,DH] fp32 (sampler input)
__device__ float g_off  [(size_t)MQ * CC];
__device__ float g_attn [(size_t)MQ * 128];
// bf16 split planes
__device__ __nv_bfloat16 g_v_hi [(size_t)MV * CC];
__device__ __nv_bfloat16 g_v_lo [(size_t)MV * CC];
__device__ __nv_bfloat16 g_q_hi [(size_t)MQ * CC];
__device__ __nv_bfloat16 g_q_lo [(size_t)MQ * CC];
__device__ __nv_bfloat16 g_s_hi [(size_t)MQ * CC];
__device__ __nv_bfloat16 g_s_lo [(size_t)MQ * CC];
// weights: wval(65536) | woff(65536) | wattn(32768) | wout(65536)
__device__ __nv_bfloat16 g_w_hi [65536 * 3 + 32768];
__device__ __nv_bfloat16 g_w_lo [65536 * 3 + 32768];

// ---------------- helpers ----------------
__device__ __forceinline__ uint32_t smem_u32(const void* p) {
    uint32_t a;
    asm("{ .reg .u64 t; cvta.to.shared.u64 t, %1; cvt.u32.u64 %0, t; }" : "=r"(a) : "l"(p));
    return a;
}
__device__ __forceinline__ void ldsm4(uint32_t* r, uint32_t addr) {
    asm volatile("ldmatrix.sync.aligned.m8n8.x4.shared.b16 {%0,%1,%2,%3}, [%4];"
        : "=r"(r[0]), "=r"(r[1]), "=r"(r[2]), "=r"(r[3]) : "r"(addr));
}
__device__ __forceinline__ void mma_bf16(float* c, const uint32_t* a, const uint32_t* b) {
    asm volatile(
        "mma.sync.aligned.m16n8k16.row.col.f32.bf16.bf16.f32 "
        "{%0,%1,%2,%3}, {%4,%5,%6,%7}, {%8,%9}, {%0,%1,%2,%3};"
        : "+f"(c[0]), "+f"(c[1]), "+f"(c[2]), "+f"(c[3])
        : "r"(a[0]), "r"(a[1]), "r"(a[2]), "r"(a[3]), "r"(b[0]), "r"(b[1]));
}
__device__ __forceinline__ void cp_async16(uint32_t dst, const void* src, uint32_t sz) {
    asm volatile("cp.async.cg.shared.global [%0], [%1], 16, %2;"
        :: "r"(dst), "l"(src), "r"(sz) : "memory");
}
#define CP_COMMIT() asm volatile("cp.async.commit_group;" ::: "memory")
#define CP_WAIT(n)  asm volatile("cp.async.wait_group %0;" :: "n"(n) : "memory")

// ---------------- fp32 -> (bf16 hi, bf16 lo) split pass ----------------
__global__ void __launch_bounds__(256) convert_split_kernel(
    const float* __restrict__ src, uint2* __restrict__ hi, uint2* __restrict__ lo, int n4)
{
    const int i = blockIdx.x * blockDim.x + threadIdx.x;
    if (i >= n4) return;
    const float4 v = ((const float4*)src)[i];
    __nv_bfloat16 h0 = __float2bfloat16(v.x), h1 = __float2bfloat16(v.y);
    __nv_bfloat16 h2 = __float2bfloat16(v.z), h3 = __float2bfloat16(v.w);
    __nv_bfloat16 l0 = __float2bfloat16(v.x - __bfloat162float(h0));
    __nv_bfloat16 l1 = __float2bfloat16(v.y - __bfloat162float(h1));
    __nv_bfloat16 l2 = __float2bfloat16(v.z - __bfloat162float(h2));
    __nv_bfloat16 l3 = __float2bfloat16(v.w - __bfloat162float(h3));
    uint2 hp, lp;
    hp.x = (uint32_t)__bfloat16_as_ushort(h0) | ((uint32_t)__bfloat16_as_ushort(h1) << 16);
    hp.y = (uint32_t)__bfloat16_as_ushort(h2) | ((uint32_t)__bfloat16_as_ushort(h3) << 16);
    lp.x = (uint32_t)__bfloat16_as_ushort(l0) | ((uint32_t)__bfloat16_as_ushort(l1) << 16);
    lp.y = (uint32_t)__bfloat16_as_ushort(l2) | ((uint32_t)__bfloat16_as_ushort(l3) << 16);
    hi[i] = hp; lo[i] = lp;
}

// ============ HMMA GEMM (pre-split bf16 operands, cp.async pipelined) ============
// C[M,N] = A[M,256] @ W[N,256]^T + bias.  Block 128x128, K stages 4 x 64, 2 buffers.
// buffer layout (per 64KB buf): Ahi[0,16K) Alo[16K,32K) Bhi[32K,48K) Blo[48K,64K)
__global__ void __launch_bounds__(256, 1) gemm_tc_kernel(
    const __nv_bfloat16* __restrict__ Ahi, const __nv_bfloat16* __restrict__ Alo,
    const __nv_bfloat16* __restrict__ Bhi, const __nv_bfloat16* __restrict__ Blo,
    const float* __restrict__ bias, float* __restrict__ Cmat,
    int M, int N)
{
    extern __shared__ char smraw[];
    char* sm = (char*)(((uintptr_t)smraw + 1023) & ~(uintptr_t)1023);
    const uint32_t su = smem_u32(sm);
    float* pbias = (float*)(sm + 131072);

    const int tid  = threadIdx.x;
    const int lane = tid & 31;
    const int warp = tid >> 5;
    const int wm = (warp >> 2) * 64;
    const int wn = (warp & 3) * 32;
    const int bm = blockIdx.y * 128;
    const int bn = blockIdx.x * 128;

    if (tid < 128) pbias[tid] = bias[bn + tid];

    float acc[4][4][4];
#pragma unroll
    for (int i = 0; i < 4; i++)
#pragma unroll
        for (int j = 0; j < 4; j++)
#pragma unroll
            for (int k = 0; k < 4; k++) acc[i][j][k] = 0.f;

    // ldmatrix lane addressing
    const uint32_t mx = (uint32_t)((lane & 7) << 4);
    uint32_t aRow[4], bRow[2];
#pragma unroll
    for (int mi = 0; mi < 4; mi++)
        aRow[mi] = (uint32_t)((wm + mi * 16 + (lane & 15)) * 128);
    const uint32_t colA = (uint32_t)((lane >> 4) * 16);
#pragma unroll
    for (int nj2 = 0; nj2 < 2; nj2++)
        bRow[nj2] = (uint32_t)((wn + nj2 * 16 + (lane & 7) + ((lane >> 4) & 1) * 8) * 128);
    const uint32_t colB = (uint32_t)(((lane >> 3) & 1) * 16);

    // ---- stage loader: 16B chunks via cp.async ----
    auto stage_load = [&](int buf, int s) {
        const uint32_t bo = su + (uint32_t)buf * 65536u;
        const int ks2 = s * 128;                       // byte offset of stage cols
#pragma unroll
        for (int it = 0; it < 4; it++) {
            const int chunk = it * 256 + tid;
            const int r = chunk >> 3, c = chunk & 7;
            const uint32_t doff = (uint32_t)(r * 128) + (uint32_t)((c * 16) ^ ((r & 7) << 4));
            const int grow = bm + r;
            const uint32_t sza = (grow < M) ? 16u : 0u;
            const size_t aoff = (size_t)grow * 512 + ks2 + c * 16;
            cp_async16(bo + doff,         (const char*)Ahi + aoff, sza);
            cp_async16(bo + 16384 + doff, (const char*)Alo + aoff, sza);
            const size_t boff = (size_t)(bn + r) * 512 + ks2 + c * 16;
            cp_async16(bo + 32768 + doff, (const char*)Bhi + boff, 16u);
            cp_async16(bo + 49152 + doff, (const char*)Blo + boff, 16u);
        }
    };

    stage_load(0, 0);
    CP_COMMIT();

    for (int s = 0; s < 4; s++) {
        if (s < 3) { stage_load((s + 1) & 1, s + 1); CP_COMMIT(); CP_WAIT(1); }
        else       { CP_WAIT(0); }
        __syncthreads();

        const uint32_t bo = su + (uint32_t)(s & 1) * 65536u;
#pragma unroll
        for (int kk = 0; kk < 4; kk++) {
            uint32_t ah[4][4], al[4][4], bh[2][4], bl[2][4];
            const uint32_t ca = ((uint32_t)(kk * 32) + colA) ^ mx;
            const uint32_t cb = ((uint32_t)(kk * 32) + colB) ^ mx;
#pragma unroll
            for (int mi = 0; mi < 4; mi++) {
                const uint32_t ad = bo + aRow[mi] + ca;
                ldsm4(ah[mi], ad);
                ldsm4(al[mi], ad + 16384);
            }
#pragma unroll
            for (int nj2 = 0; nj2 < 2; nj2++) {
                const uint32_t bd = bo + 32768 + bRow[nj2] + cb;
                ldsm4(bh[nj2], bd);
                ldsm4(bl[nj2], bd + 16384);
            }
#pragma unroll
            for (int mi = 0; mi < 4; mi++) {
#pragma unroll
                for (int nj = 0; nj < 4; nj++) {
                    const uint32_t* bfh = &bh[nj >> 1][(nj & 1) * 2];
                    const uint32_t* bfl = &bl[nj >> 1][(nj & 1) * 2];
                    mma_bf16(acc[mi][nj], ah[mi], bfh);
                    mma_bf16(acc[mi][nj], ah[mi], bfl);
                    mma_bf16(acc[mi][nj], al[mi], bfh);
                }
            }
        }
        __syncthreads();
    }

    // ---- epilogue ----
    const int r0 = lane >> 2;
    const int c0 = (lane & 3) * 2;
#pragma unroll
    for (int mi = 0; mi < 4; mi++) {
        const int gm = bm + wm + mi * 16 + r0;
#pragma unroll
        for (int half = 0; half < 2; half++) {
            const int gmr = gm + half * 8;
            if (gmr < M) {
                float* op = Cmat + (size_t)gmr * N + bn;
#pragma unroll
                for (int nj = 0; nj < 4; nj++) {
                    const int cl = wn + nj * 8 + c0;
                    float2 o;
                    o.x = acc[mi][nj][half * 2 + 0] + pbias[cl];
                    o.y = acc[mi][nj][half * 2 + 1] + pbias[cl + 1];
                    *(float2*)(op + cl) = o;
                }
            }
        }
    }
}

// ---------------- sampling: softmax + bilinear gather -------------------
// one warp per (b,q,h). lanes 0..15 own one (level,point); gather lane=channel.
__global__ void __launch_bounds__(256) sample_kernel(
    const float* __restrict__ ref)
{
    constexpr int LH[4]  = {100, 50, 25, 13};
    constexpr int LW[4]  = {150, 75, 38, 19};
    constexpr int LST[4] = {0, 15000, 18750, 19700};

    const int warp = (blockIdx.x * blockDim.x + threadIdx.x) >> 5;
    const int lane = threadIdx.x & 31;
    if (warp >= BB * NQ * NHD) return;

    const int h  = warp % NHD;
    const int bq = warp / NHD;
    const int b  = bq / NQ;
    const int sl = (lane >> 2) & 3;

    // softmax over 16 logits, one per lane
    const float* logit = g_attn + (size_t)bq * 128 + h * 16;
    float lg = (lane < 16) ? logit[lane] : -1e30f;
    float mxv = lg;
#pragma unroll
    for (int o = 8; o; o >>= 1) mxv = fmaxf(mxv, __shfl_xor_sync(0xffffffffu, mxv, o, 16));
    float ev = __expf(lg - mxv);
    float sum = ev;
#pragma unroll
    for (int o = 8; o; o >>= 1) sum += __shfl_xor_sync(0xffffffffu, sum, o, 16);
    const float aw = ev / sum;

    // per-lane sample coords
    const float2 off2 = ((const float2*)(g_off + (size_t)bq * 256 + h * 32))[lane & 15];
    const float2 rxy  = ((const float2*)(ref + (size_t)bq * 8))[sl];
    const float fW = (float)LW[sl], fH = (float)LH[sl];
    const float x = (rxy.x + off2.x / fW) * fW - 0.5f;
    const float y = (rxy.y + off2.y / fH) * fH - 0.5f;
    const float x0f = floorf(x), y0f = floorf(y);
    const float wx1 = x - x0f, wy1 = y - y0f;
    const int pk = (((int)y0f) << 16) | (((int)x0f) & 0xffff);

    float accv = 0.f;
#pragma unroll
    for (int l = 0; l < 4; l++) {
        const int W = LW[l], H = LH[l];
        const float* vbase = g_value
            + ((size_t)(b * S_TOT + LST[l]) * NHD + h) * DH + lane;
#pragma unroll
        for (int p = 0; p < 4; p++) {
            const int s = l * 4 + p;
            const int   bpk = __shfl_sync(0xffffffffu, pk,  s);
            const float bwx = __shfl_sync(0xffffffffu, wx1, s);
            const float bwy = __shfl_sync(0xffffffffu, wy1, s);
            const float baw = __shfl_sync(0xffffffffu, aw,  s);
            const int bix = (int)(short)(bpk & 0xffff);
            const int biy = bpk >> 16;
            const float wy0a = (1.f - bwy) * baw;
            const float wy1a = bwy * baw;
            const float wx0 = 1.f - bwx;
            const bool xi0 = (unsigned)bix < (unsigned)W;
            const bool xi1 = (unsigned)(bix + 1) < (unsigned)W;
            const bool yi0 = (unsigned)biy < (unsigned)H;
            const bool yi1 = (unsigned)(biy + 1) < (unsigned)H;
            const float* pp = vbase + (ptrdiff_t)(biy * W + bix) * 256;
            if (yi0 && xi0) accv += (wx0 * wy0a) * __ldg(pp);
            if (yi0 && xi1) accv += (bwx * wy0a) * __ldg(pp + 256);
            if (yi1 && xi0) accv += (wx0 * wy1a) * __ldg(pp + W * 256);
            if (yi1 && xi1) accv += (bwx * wy1a) * __ldg(pp + W * 256 + 256);
        }
    }
    const int idx = (bq * NHD + h) * DH + lane;
    __nv_bfloat16 hv = __float2bfloat16(accv);
    __nv_bfloat16 lv = __float2bfloat16(accv - __bfloat162float(hv));
    g_s_hi[idx] = hv;
    g_s_lo[idx] = lv;
}

// ---------------- launch ----------------
#define GEMM_SMEM_BYTES 133120

extern "C" void kernel_launch(void* const* d_in, const int* in_sizes, int n_in,
                              void* d_out, int out_size)
{
    (void)in_sizes; (void)n_in; (void)out_size;
    const float* query  = (const float*)d_in[0];
    const float* vlv    = (const float*)d_in[1];
    const float* refpts = (const float*)d_in[2];
    const float* W_off  = (const float*)d_in[4];
    const float* b_off  = (const float*)d_in[5];
    const float* W_attn = (const float*)d_in[6];
    const float* b_attn = (const float*)d_in[7];
    const float* W_val  = (const float*)d_in[8];
    const float* b_val  = (const float*)d_in[9];
    const float* W_out  = (const float*)d_in[10];
    const float* b_out  = (const float*)d_in[11];
    float* out = (float*)d_out;

    cudaFuncSetAttribute(gemm_tc_kernel,
                         cudaFuncAttributeMaxDynamicSharedMemorySize, GEMM_SMEM_BYTES);

    float *p_value, *p_off, *p_attn;
    __nv_bfloat16 *p_vhi, *p_vlo, *p_qhi, *p_qlo, *p_shi, *p_slo, *p_whi, *p_wlo;
    cudaGetSymbolAddress((void**)&p_value, g_value);
    cudaGetSymbolAddress((void**)&p_off,   g_off);
    cudaGetSymbolAddress((void**)&p_attn,  g_attn);
    cudaGetSymbolAddress((void**)&p_vhi,   g_v_hi);
    cudaGetSymbolAddress((void**)&p_vlo,   g_v_lo);
    cudaGetSymbolAddress((void**)&p_qhi,   g_q_hi);
    cudaGetSymbolAddress((void**)&p_qlo,   g_q_lo);
    cudaGetSymbolAddress((void**)&p_shi,   g_s_hi);
    cudaGetSymbolAddress((void**)&p_slo,   g_s_lo);
    cudaGetSymbolAddress((void**)&p_whi,   g_w_hi);
    cudaGetSymbolAddress((void**)&p_wlo,   g_w_lo);

    // weight plane offsets
    __nv_bfloat16 *wv_hi = p_whi,            *wv_lo = p_wlo;
    __nv_bfloat16 *wo_hi = p_whi + 65536,    *wo_lo = p_wlo + 65536;
    __nv_bfloat16 *wa_hi = p_whi + 131072,   *wa_lo = p_wlo + 131072;
    __nv_bfloat16 *wu_hi = p_whi + 163840,   *wu_lo = p_wlo + 163840;

    // ---- conversion passes ----
    {
        int n4 = MV * CC / 4;
        convert_split_kernel<<<(n4 + 255) / 256, 256>>>(vlv, (uint2*)p_vhi, (uint2*)p_vlo, n4);
    }
    {
        int n4 = MQ * CC / 4;
        convert_split_kernel<<<(n4 + 255) / 256, 256>>>(query, (uint2*)p_qhi, (uint2*)p_qlo, n4);
    }
    convert_split_kernel<<<64, 256>>>(W_val,  (uint2*)wv_hi, (uint2*)wv_lo, 16384);
    convert_split_kernel<<<64, 256>>>(W_off,  (uint2*)wo_hi, (uint2*)wo_lo, 16384);
    convert_split_kernel<<<32, 256>>>(W_attn, (uint2*)wa_hi, (uint2*)wa_lo, 8192);
    convert_split_kernel<<<64, 256>>>(W_out,  (uint2*)wu_hi, (uint2*)wu_lo, 16384);

    // ---- GEMMs + sampling ----
    { dim3 g(2, (MV + 127) / 128); gemm_tc_kernel<<<g, 256, GEMM_SMEM_BYTES>>>(p_vhi, p_vlo, wv_hi, wv_lo, b_val,  p_value, MV, 256); }
    { dim3 g(2, (MQ + 127) / 128); gemm_tc_kernel<<<g, 256, GEMM_SMEM_BYTES>>>(p_qhi, p_qlo, wo_hi, wo_lo, b_off,  p_off,   MQ, 256); }
    { dim3 g(1, (MQ + 127) / 128); gemm_tc_kernel<<<g, 256, GEMM_SMEM_BYTES>>>(p_qhi, p_qlo, wa_hi, wa_lo, b_attn, p_attn,  MQ, 128); }
    {
        const int nwarp = BB * NQ * NHD;
        sample_kernel<<<(nwarp * 32 + 255) / 256, 256>>>(refpts);
    }
    { dim3 g(2, (MQ + 127) / 128); gemm_tc_kernel<<<g, 256, GEMM_SMEM_BYTES>>>(p_shi, p_slo, wu_hi, wu_lo, b_out,  out,     MQ, 256); }
}

// round 5
// speedup vs baseline: 2.6112x; 1.1088x over previous
#include <cuda_runtime.h>
#include <cuda_bf16.h>
#include <cstdint>
#include <math.h>

// ---------------- problem constants ----------------
#define BB   4
#define NQ   8000
#define CC   256
#define NHD  8
#define NLV  4
#define NPT  4
#define DH   32
#define S_TOT 19947

#define MV (BB * S_TOT)   // 79788
#define MQ (BB * NQ)      // 32000

// ---------------- scratch ----------------
__device__ float g_value[(size_t)MV * CC];           // [B,S,NH,DH] fp32 (sampler gather src)
__device__ float g_qout [(size_t)MQ * 384];          // fused: [0,256)=offsets, [256,384)=logits
// bf16 split planes
__device__ __nv_bfloat16 g_v_hi [(size_t)MV * CC];
__device__ __nv_bfloat16 g_v_lo [(size_t)MV * CC];
__device__ __nv_bfloat16 g_q_hi [(size_t)MQ * CC];
__device__ __nv_bfloat16 g_q_lo [(size_t)MQ * CC];
__device__ __nv_bfloat16 g_s_hi [(size_t)MQ * CC];
__device__ __nv_bfloat16 g_s_lo [(size_t)MQ * CC];
// weights: wval(65536) | qw fused(98304 = 256*256 off + 128*256 attn) | wout(65536)
__device__ __nv_bfloat16 g_w_hi [65536 + 98304 + 65536];
__device__ __nv_bfloat16 g_w_lo [65536 + 98304 + 65536];
__device__ float g_qb[384];                          // fused bias for q GEMM

// ---------------- helpers ----------------
__device__ __forceinline__ uint32_t smem_u32(const void* p) {
    uint32_t a;
    asm("{ .reg .u64 t; cvta.to.shared.u64 t, %1; cvt.u32.u64 %0, t; }" : "=r"(a) : "l"(p));
    return a;
}
__device__ __forceinline__ void ldsm4(uint32_t* r, uint32_t addr) {
    asm volatile("ldmatrix.sync.aligned.m8n8.x4.shared.b16 {%0,%1,%2,%3}, [%4];"
        : "=r"(r[0]), "=r"(r[1]), "=r"(r[2]), "=r"(r[3]) : "r"(addr));
}
__device__ __forceinline__ void mma_bf16(float* c, const uint32_t* a, const uint32_t* b) {
    asm volatile(
        "mma.sync.aligned.m16n8k16.row.col.f32.bf16.bf16.f32 "
        "{%0,%1,%2,%3}, {%4,%5,%6,%7}, {%8,%9}, {%0,%1,%2,%3};"
        : "+f"(c[0]), "+f"(c[1]), "+f"(c[2]), "+f"(c[3])
        : "r"(a[0]), "r"(a[1]), "r"(a[2]), "r"(a[3]), "r"(b[0]), "r"(b[1]));
}
__device__ __forceinline__ void cp_async16(uint32_t dst, const void* src, uint32_t sz) {
    asm volatile("cp.async.cg.shared.global [%0], [%1], 16, %2;"
        :: "r"(dst), "l"(src), "r"(sz) : "memory");
}
#define CP_COMMIT() asm volatile("cp.async.commit_group;" ::: "memory")
#define CP_WAIT(n)  asm volatile("cp.async.wait_group %0;" :: "n"(n) : "memory")

// ---------------- fp32 -> (bf16 hi, bf16 lo) split pass ----------------
__global__ void __launch_bounds__(256) convert_split_kernel(
    const float* __restrict__ src, uint2* __restrict__ hi, uint2* __restrict__ lo, int n4)
{
    const int i = blockIdx.x * blockDim.x + threadIdx.x;
    if (i >= n4) return;
    const float4 v = ((const float4*)src)[i];
    __nv_bfloat16 h0 = __float2bfloat16(v.x), h1 = __float2bfloat16(v.y);
    __nv_bfloat16 h2 = __float2bfloat16(v.z), h3 = __float2bfloat16(v.w);
    __nv_bfloat16 l0 = __float2bfloat16(v.x - __bfloat162float(h0));
    __nv_bfloat16 l1 = __float2bfloat16(v.y - __bfloat162float(h1));
    __nv_bfloat16 l2 = __float2bfloat16(v.z - __bfloat162float(h2));
    __nv_bfloat16 l3 = __float2bfloat16(v.w - __bfloat162float(h3));
    uint2 hp, lp;
    hp.x = (uint32_t)__bfloat16_as_ushort(h0) | ((uint32_t)__bfloat16_as_ushort(h1) << 16);
    hp.y = (uint32_t)__bfloat16_as_ushort(h2) | ((uint32_t)__bfloat16_as_ushort(h3) << 16);
    lp.x = (uint32_t)__bfloat16_as_ushort(l0) | ((uint32_t)__bfloat16_as_ushort(l1) << 16);
    lp.y = (uint32_t)__bfloat16_as_ushort(l2) | ((uint32_t)__bfloat16_as_ushort(l3) << 16);
    hi[i] = hp; lo[i] = lp;
}

__global__ void fuse_bias_kernel(const float* __restrict__ b_off, const float* __restrict__ b_attn)
{
    const int i = threadIdx.x;
    g_qb[i] = (i < 256) ? b_off[i] : b_attn[i - 256];
}

// ============ HMMA GEMM (pre-split bf16 operands, cp.async pipelined) ============
__global__ void __launch_bounds__(256, 1) gemm_tc_kernel(
    const __nv_bfloat16* __restrict__ Ahi, const __nv_bfloat16* __restrict__ Alo,
    const __nv_bfloat16* __restrict__ Bhi, const __nv_bfloat16* __restrict__ Blo,
    const float* __restrict__ bias, float* __restrict__ Cmat,
    int M, int N)
{
    extern __shared__ char smraw[];
    char* sm = (char*)(((uintptr_t)smraw + 1023) & ~(uintptr_t)1023);
    const uint32_t su = smem_u32(sm);
    float* pbias = (float*)(sm + 131072);

    const int tid  = threadIdx.x;
    const int lane = tid & 31;
    const int warp = tid >> 5;
    const int wm = (warp >> 2) * 64;
    const int wn = (warp & 3) * 32;
    const int bm = blockIdx.y * 128;
    const int bn = blockIdx.x * 128;

    if (tid < 128) pbias[tid] = bias[bn + tid];

    float acc[4][4][4];
#pragma unroll
    for (int i = 0; i < 4; i++)
#pragma unroll
        for (int j = 0; j < 4; j++)
#pragma unroll
            for (int k = 0; k < 4; k++) acc[i][j][k] = 0.f;

    const uint32_t mx = (uint32_t)((lane & 7) << 4);
    uint32_t aRow[4], bRow[2];
#pragma unroll
    for (int mi = 0; mi < 4; mi++)
        aRow[mi] = (uint32_t)((wm + mi * 16 + (lane & 15)) * 128);
    const uint32_t colA = (uint32_t)((lane >> 4) * 16);
#pragma unroll
    for (int nj2 = 0; nj2 < 2; nj2++)
        bRow[nj2] = (uint32_t)((wn + nj2 * 16 + (lane & 7) + ((lane >> 4) & 1) * 8) * 128);
    const uint32_t colB = (uint32_t)(((lane >> 3) & 1) * 16);

    auto stage_load = [&](int buf, int s) {
        const uint32_t bo = su + (uint32_t)buf * 65536u;
        const int ks2 = s * 128;
#pragma unroll
        for (int it = 0; it < 4; it++) {
            const int chunk = it * 256 + tid;
            const int r = chunk >> 3, c = chunk & 7;
            const uint32_t doff = (uint32_t)(r * 128) + (uint32_t)((c * 16) ^ ((r & 7) << 4));
            const int grow = bm + r;
            const uint32_t sza = (grow < M) ? 16u : 0u;
            const size_t aoff = (size_t)grow * 512 + ks2 + c * 16;
            cp_async16(bo + doff,         (const char*)Ahi + aoff, sza);
            cp_async16(bo + 16384 + doff, (const char*)Alo + aoff, sza);
            const size_t boff = (size_t)(bn + r) * 512 + ks2 + c * 16;
            cp_async16(bo + 32768 + doff, (const char*)Bhi + boff, 16u);
            cp_async16(bo + 49152 + doff, (const char*)Blo + boff, 16u);
        }
    };

    stage_load(0, 0);
    CP_COMMIT();

    for (int s = 0; s < 4; s++) {
        if (s < 3) { stage_load((s + 1) & 1, s + 1); CP_COMMIT(); CP_WAIT(1); }
        else       { CP_WAIT(0); }
        __syncthreads();

        const uint32_t bo = su + (uint32_t)(s & 1) * 65536u;
#pragma unroll
        for (int kk = 0; kk < 4; kk++) {
            uint32_t ah[4][4], al[4][4], bh[2][4], bl[2][4];
            const uint32_t ca = ((uint32_t)(kk * 32) + colA) ^ mx;
            const uint32_t cb = ((uint32_t)(kk * 32) + colB) ^ mx;
#pragma unroll
            for (int mi = 0; mi < 4; mi++) {
                const uint32_t ad = bo + aRow[mi] + ca;
                ldsm4(ah[mi], ad);
                ldsm4(al[mi], ad + 16384);
            }
#pragma unroll
            for (int nj2 = 0; nj2 < 2; nj2++) {
                const uint32_t bd = bo + 32768 + bRow[nj2] + cb;
                ldsm4(bh[nj2], bd);
                ldsm4(bl[nj2], bd + 16384);
            }
#pragma unroll
            for (int mi = 0; mi < 4; mi++) {
#pragma unroll
                for (int nj = 0; nj < 4; nj++) {
                    const uint32_t* bfh = &bh[nj >> 1][(nj & 1) * 2];
                    const uint32_t* bfl = &bl[nj >> 1][(nj & 1) * 2];
                    mma_bf16(acc[mi][nj], ah[mi], bfh);
                    mma_bf16(acc[mi][nj], ah[mi], bfl);
                    mma_bf16(acc[mi][nj], al[mi], bfh);
                }
            }
        }
        __syncthreads();
    }

    const int r0 = lane >> 2;
    const int c0 = (lane & 3) * 2;
#pragma unroll
    for (int mi = 0; mi < 4; mi++) {
        const int gm = bm + wm + mi * 16 + r0;
#pragma unroll
        for (int half = 0; half < 2; half++) {
            const int gmr = gm + half * 8;
            if (gmr < M) {
                float* op = Cmat + (size_t)gmr * N + bn;
#pragma unroll
                for (int nj = 0; nj < 4; nj++) {
                    const int cl = wn + nj * 8 + c0;
                    float2 o;
                    o.x = acc[mi][nj][half * 2 + 0] + pbias[cl];
                    o.y = acc[mi][nj][half * 2 + 1] + pbias[cl + 1];
                    *(float2*)(op + cl) = o;
                }
            }
        }
    }
}

// ---------------- sampling: softmax + paired bilinear gather -------------
// one warp per (b,q,h). lanes 0..15 compute one sample's coords each.
// gather: sample pair per step; half = lane>>4 selects sample, (lane&15) = channel pair.
__global__ void __launch_bounds__(256) sample_kernel(
    const float* __restrict__ ref)
{
    constexpr int LH[4]  = {100, 50, 25, 13};
    constexpr int LW[4]  = {150, 75, 38, 19};
    constexpr int LST[4] = {0, 15000, 18750, 19700};

    const int warp = (blockIdx.x * blockDim.x + threadIdx.x) >> 5;
    const int lane = threadIdx.x & 31;
    if (warp >= BB * NQ * NHD) return;

    const int h  = warp % NHD;
    const int bq = warp / NHD;
    const int b  = bq / NQ;
    const int sl = (lane >> 2) & 3;   // lane's sample level (lanes 0..15)

    const float* qrow = g_qout + (size_t)bq * 384;

    // softmax over 16 logits, one per lane
    const float* logit = qrow + 256 + h * 16;
    float lg = (lane < 16) ? logit[lane] : -1e30f;
    float mxv = lg;
#pragma unroll
    for (int o = 8; o; o >>= 1) mxv = fmaxf(mxv, __shfl_xor_sync(0xffffffffu, mxv, o, 16));
    float ev = __expf(lg - mxv);
    float sum = ev;
#pragma unroll
    for (int o = 8; o; o >>= 1) sum += __shfl_xor_sync(0xffffffffu, sum, o, 16);
    const float aw = ev / sum;

    // per-lane sample coords (lanes 0..15 meaningful)
    const float2 off2 = ((const float2*)(qrow + h * 32))[lane & 15];
    const float2 rxy  = ((const float2*)(ref + (size_t)bq * 8))[sl];
    const float fW = (float)LW[sl], fH = (float)LH[sl];
    const float x = (rxy.x + off2.x / fW) * fW - 0.5f;
    const float y = (rxy.y + off2.y / fH) * fH - 0.5f;
    const float x0f = floorf(x), y0f = floorf(y);
    const float wx1 = x - x0f, wy1 = y - y0f;
    const int pk = (((int)y0f) << 16) | (((int)x0f) & 0xffff);

    // gather phase: 8 sample pairs; this lane serves sample (2*sp + half)
    const int half = lane >> 4;            // 0 or 1
    const int chan = (lane & 15) * 2;      // channel pair
    float ax = 0.f, ay = 0.f;

#pragma unroll
    for (int l = 0; l < 4; l++) {
        const int W = LW[l], H = LH[l];
        const float* vbase = g_value
            + ((size_t)(b * S_TOT + LST[l]) * NHD + h) * DH + chan;
#pragma unroll
        for (int pp = 0; pp < 2; pp++) {
            const int sp  = l * 2 + pp;
            const int src = sp * 2 + half;      // sample index owned by lane 'src'
            const int   bpk = __shfl_sync(0xffffffffu, pk,  src);
            const float bwx = __shfl_sync(0xffffffffu, wx1, src);
            const float bwy = __shfl_sync(0xffffffffu, wy1, src);
            const float baw = __shfl_sync(0xffffffffu, aw,  src);
            const int bix = (int)(short)(bpk & 0xffff);
            const int biy = bpk >> 16;
            const float wy0a = (1.f - bwy) * baw;
            const float wy1a = bwy * baw;
            const float wx0 = 1.f - bwx;
            const bool xi0 = (unsigned)bix < (unsigned)W;
            const bool xi1 = (unsigned)(bix + 1) < (unsigned)W;
            const bool yi0 = (unsigned)biy < (unsigned)H;
            const bool yi1 = (unsigned)(biy + 1) < (unsigned)H;
            const float* pp0 = vbase + (ptrdiff_t)(biy * W + bix) * 256;
            if (yi0 && xi0) { const float2 v = *(const float2*)pp0;
                const float w = wx0 * wy0a; ax = fmaf(w, v.x, ax); ay = fmaf(w, v.y, ay); }
            if (yi0 && xi1) { const float2 v = *(const float2*)(pp0 + 256);
                const float w = bwx * wy0a; ax = fmaf(w, v.x, ax); ay = fmaf(w, v.y, ay); }
            if (yi1 && xi0) { const float2 v = *(const float2*)(pp0 + W * 256);
                const float w = wx0 * wy1a; ax = fmaf(w, v.x, ax); ay = fmaf(w, v.y, ay); }
            if (yi1 && xi1) { const float2 v = *(const float2*)(pp0 + W * 256 + 256);
                const float w = bwx * wy1a; ax = fmaf(w, v.x, ax); ay = fmaf(w, v.y, ay); }
        }
    }
    // combine the two halves (even samples in lanes 0-15, odd in 16-31)
    ax += __shfl_xor_sync(0xffffffffu, ax, 16);
    ay += __shfl_xor_sync(0xffffffffu, ay, 16);

    if (lane < 16) {
        __nv_bfloat16 hx = __float2bfloat16(ax);
        __nv_bfloat16 hy = __float2bfloat16(ay);
        __nv_bfloat16 lx = __float2bfloat16(ax - __bfloat162float(hx));
        __nv_bfloat16 ly = __float2bfloat16(ay - __bfloat162float(hy));
        const size_t idx = ((size_t)(bq * NHD + h) * DH + chan) >> 1;  // uint32 index
        ((uint32_t*)g_s_hi)[idx] = (uint32_t)__bfloat16_as_ushort(hx) | ((uint32_t)__bfloat16_as_ushort(hy) << 16);
        ((uint32_t*)g_s_lo)[idx] = (uint32_t)__bfloat16_as_ushort(lx) | ((uint32_t)__bfloat16_as_ushort(ly) << 16);
    }
}

// ---------------- launch ----------------
#define GEMM_SMEM_BYTES 133120

extern "C" void kernel_launch(void* const* d_in, const int* in_sizes, int n_in,
                              void* d_out, int out_size)
{
    (void)in_sizes; (void)n_in; (void)out_size;
    const float* query  = (const float*)d_in[0];
    const float* vlv    = (const float*)d_in[1];
    const float* refpts = (const float*)d_in[2];
    const float* W_off  = (const float*)d_in[4];
    const float* b_off  = (const float*)d_in[5];
    const float* W_attn = (const float*)d_in[6];
    const float* b_attn = (const float*)d_in[7];
    const float* W_val  = (const float*)d_in[8];
    const float* b_val  = (const float*)d_in[9];
    const float* W_out  = (const float*)d_in[10];
    const float* b_out  = (const float*)d_in[11];
    float* out = (float*)d_out;

    cudaFuncSetAttribute(gemm_tc_kernel,
                         cudaFuncAttributeMaxDynamicSharedMemorySize, GEMM_SMEM_BYTES);

    float *p_value, *p_qout, *p_qb;
    __nv_bfloat16 *p_vhi, *p_vlo, *p_qhi, *p_qlo, *p_shi, *p_slo, *p_whi, *p_wlo;
    cudaGetSymbolAddress((void**)&p_value, g_value);
    cudaGetSymbolAddress((void**)&p_qout,  g_qout);
    cudaGetSymbolAddress((void**)&p_qb,    g_qb);
    cudaGetSymbolAddress((void**)&p_vhi,   g_v_hi);
    cudaGetSymbolAddress((void**)&p_vlo,   g_v_lo);
    cudaGetSymbolAddress((void**)&p_qhi,   g_q_hi);
    cudaGetSymbolAddress((void**)&p_qlo,   g_q_lo);
    cudaGetSymbolAddress((void**)&p_shi,   g_s_hi);
    cudaGetSymbolAddress((void**)&p_slo,   g_s_lo);
    cudaGetSymbolAddress((void**)&p_whi,   g_w_hi);
    cudaGetSymbolAddress((void**)&p_wlo,   g_w_lo);

    // weight plane offsets: wval | qw (off 256 rows + attn 128 rows) | wout
    __nv_bfloat16 *wv_hi = p_whi,           *wv_lo = p_wlo;
    __nv_bfloat16 *qw_hi = p_whi + 65536,   *qw_lo = p_wlo + 65536;
    __nv_bfloat16 *wu_hi = p_whi + 163840,  *wu_lo = p_wlo + 163840;

    // ---- conversion passes ----
    {
        int n4 = MV * CC / 4;
        convert_split_kernel<<<(n4 + 255) / 256, 256>>>(vlv, (uint2*)p_vhi, (uint2*)p_vlo, n4);
    }
    {
        int n4 = MQ * CC / 4;
        convert_split_kernel<<<(n4 + 255) / 256, 256>>>(query, (uint2*)p_qhi, (uint2*)p_qlo, n4);
    }
    convert_split_kernel<<<64, 256>>>(W_val,  (uint2*)wv_hi, (uint2*)wv_lo, 16384);
    convert_split_kernel<<<64, 256>>>(W_off,  (uint2*)qw_hi, (uint2*)qw_lo, 16384);
    convert_split_kernel<<<32, 256>>>(W_attn, (uint2*)(qw_hi + 65536), (uint2*)(qw_lo + 65536), 8192);
    convert_split_kernel<<<64, 256>>>(W_out,  (uint2*)wu_hi, (uint2*)wu_lo, 16384);
    fuse_bias_kernel<<<1, 384>>>(b_off, b_attn);

    // ---- GEMMs + sampling ----
    { dim3 g(2, (MV + 127) / 128); gemm_tc_kernel<<<g, 256, GEMM_SMEM_BYTES>>>(p_vhi, p_vlo, wv_hi, wv_lo, b_val, p_value, MV, 256); }
    { dim3 g(3, (MQ + 127) / 128); gemm_tc_kernel<<<g, 256, GEMM_SMEM_BYTES>>>(p_qhi, p_qlo, qw_hi, qw_lo, p_qb,  p_qout,  MQ, 384); }
    {
        const int nwarp = BB * NQ * NHD;
        sample_kernel<<<(nwarp * 32 + 255) / 256, 256>>>(refpts);
    }
    { dim3 g(2, (MQ + 127) / 128); gemm_tc_kernel<<<g, 256, GEMM_SMEM_BYTES>>>(p_shi, p_slo, wu_hi, wu_lo, b_out, out,     MQ, 256); }
}

// round 7
// speedup vs baseline: 2.7322x; 1.0463x over previous
#include <cuda_runtime.h>
#include <cuda_bf16.h>
#include <cstdint>
#include <math.h>

// ---------------- problem constants ----------------
#define BB   4
#define NQ   8000
#define CC   256
#define NHD  8
#define NLV  4
#define NPT  4
#define DH   32
#define S_TOT 19947

#define MV (BB * S_TOT)   // 79788
#define MQ (BB * NQ)      // 32000

// ---------------- scratch ----------------
__device__ float g_value[(size_t)MV * CC];           // [B,S,NH,DH] fp32 (sampler gather src)
__device__ float g_qout [(size_t)MQ * 384];          // fused: [0,256)=offsets, [256,384)=logits
__device__ __nv_bfloat16 g_v_hi [(size_t)MV * CC];
__device__ __nv_bfloat16 g_v_lo [(size_t)MV * CC];
__device__ __nv_bfloat16 g_q_hi [(size_t)MQ * CC];
__device__ __nv_bfloat16 g_q_lo [(size_t)MQ * CC];
__device__ __nv_bfloat16 g_s_hi [(size_t)MQ * CC];
__device__ __nv_bfloat16 g_s_lo [(size_t)MQ * CC];
// weights: wval(65536) | qw fused(98304) | wout(65536)
__device__ __nv_bfloat16 g_w_hi [65536 + 98304 + 65536];
__device__ __nv_bfloat16 g_w_lo [65536 + 98304 + 65536];
__device__ float g_qb[384];

// ---------------- helpers ----------------
__device__ __forceinline__ uint32_t smem_u32(const void* p) {
    uint32_t a;
    asm("{ .reg .u64 t; cvta.to.shared.u64 t, %1; cvt.u32.u64 %0, t; }" : "=r"(a) : "l"(p));
    return a;
}
__device__ __forceinline__ void ldsm4(uint32_t* r, uint32_t addr) {
    asm volatile("ldmatrix.sync.aligned.m8n8.x4.shared.b16 {%0,%1,%2,%3}, [%4];"
        : "=r"(r[0]), "=r"(r[1]), "=r"(r[2]), "=r"(r[3]) : "r"(addr));
}
__device__ __forceinline__ void mma_bf16(float* c, const uint32_t* a, const uint32_t* b) {
    asm volatile(
        "mma.sync.aligned.m16n8k16.row.col.f32.bf16.bf16.f32 "
        "{%0,%1,%2,%3}, {%4,%5,%6,%7}, {%8,%9}, {%0,%1,%2,%3};"
        : "+f"(c[0]), "+f"(c[1]), "+f"(c[2]), "+f"(c[3])
        : "r"(a[0]), "r"(a[1]), "r"(a[2]), "r"(a[3]), "r"(b[0]), "r"(b[1]));
}
__device__ __forceinline__ void cp_async16(uint32_t dst, const void* src, uint32_t sz) {
    asm volatile("cp.async.cg.shared.global [%0], [%1], 16, %2;"
        :: "r"(dst), "l"(src), "r"(sz) : "memory");
}
#define CP_COMMIT() asm volatile("cp.async.commit_group;" ::: "memory")
#define CP_WAIT(n)  asm volatile("cp.async.wait_group %0;" :: "n"(n) : "memory")

// ---------------- mega conversion kernel -------------------------------
#define NB_V  (MV / 4)        // 19947
#define NB_Q  (MQ / 4)        // 8000
#define NB_WV 64
#define NB_WO 64
#define NB_WA 32
#define NB_WU 64
#define NB_TOT (NB_V + NB_Q + NB_WV + NB_WO + NB_WA + NB_WU + 1)

struct ConvArgs {
    const float *vlv, *query, *w_val, *w_off, *w_attn, *w_out, *b_off, *b_attn;
};

__global__ void __launch_bounds__(256) convert_all_kernel(ConvArgs a)
{
    const int blk = blockIdx.x;
    const int tid = threadIdx.x;

    const float* src;
    uint2 *hi, *lo;
    int rel;

    if (blk < NB_V) {
        src = a.vlv; hi = (uint2*)g_v_hi; lo = (uint2*)g_v_lo; rel = blk;
    } else if (blk < NB_V + NB_Q) {
        src = a.query; hi = (uint2*)g_q_hi; lo = (uint2*)g_q_lo; rel = blk - NB_V;
    } else if (blk < NB_V + NB_Q + NB_WV) {
        src = a.w_val; hi = (uint2*)g_w_hi; lo = (uint2*)g_w_lo; rel = blk - (NB_V + NB_Q);
    } else if (blk < NB_V + NB_Q + NB_WV + NB_WO) {
        src = a.w_off; hi = (uint2*)(g_w_hi + 65536); lo = (uint2*)(g_w_lo + 65536);
        rel = blk - (NB_V + NB_Q + NB_WV);
    } else if (blk < NB_V + NB_Q + NB_WV + NB_WO + NB_WA) {
        src = a.w_attn; hi = (uint2*)(g_w_hi + 131072); lo = (uint2*)(g_w_lo + 131072);
        rel = blk - (NB_V + NB_Q + NB_WV + NB_WO);
    } else if (blk < NB_V + NB_Q + NB_WV + NB_WO + NB_WA + NB_WU) {
        src = a.w_out; hi = (uint2*)(g_w_hi + 163840); lo = (uint2*)(g_w_lo + 163840);
        rel = blk - (NB_V + NB_Q + NB_WV + NB_WO + NB_WA);
    } else {
        // bias fuse: block has 256 threads, 384 entries -> loop (R6 bug was `if (tid<384)`)
        for (int i = tid; i < 384; i += 256)
            g_qb[i] = (i < 256) ? a.b_off[i] : a.b_attn[i - 256];
        return;
    }

    const int i = rel * 256 + tid;
    const float4 v = ((const float4*)src)[i];
    __nv_bfloat16 h0 = __float2bfloat16(v.x), h1 = __float2bfloat16(v.y);
    __nv_bfloat16 h2 = __float2bfloat16(v.z), h3 = __float2bfloat16(v.w);
    __nv_bfloat16 l0 = __float2bfloat16(v.x - __bfloat162float(h0));
    __nv_bfloat16 l1 = __float2bfloat16(v.y - __bfloat162float(h1));
    __nv_bfloat16 l2 = __float2bfloat16(v.z - __bfloat162float(h2));
    __nv_bfloat16 l3 = __float2bfloat16(v.w - __bfloat162float(h3));
    uint2 hp, lp;
    hp.x = (uint32_t)__bfloat16_as_ushort(h0) | ((uint32_t)__bfloat16_as_ushort(h1) << 16);
    hp.y = (uint32_t)__bfloat16_as_ushort(h2) | ((uint32_t)__bfloat16_as_ushort(h3) << 16);
    lp.x = (uint32_t)__bfloat16_as_ushort(l0) | ((uint32_t)__bfloat16_as_ushort(l1) << 16);
    lp.y = (uint32_t)__bfloat16_as_ushort(l2) | ((uint32_t)__bfloat16_as_ushort(l3) << 16);
    hi[i] = hp; lo[i] = lp;
}

// ============ HMMA GEMM, two independent segments in one grid ============
struct GemmSeg {
    const __nv_bfloat16 *Ahi, *Alo, *Bhi, *Blo;
    const float* bias;
    float* C;
    int M, N, ntiles, tilesPerRow;
};

__global__ void __launch_bounds__(256, 1) gemm_tc2_kernel(GemmSeg s0, GemmSeg s1)
{
    extern __shared__ char smraw[];
    char* sm = (char*)(((uintptr_t)smraw + 1023) & ~(uintptr_t)1023);
    const uint32_t su = smem_u32(sm);
    float* pbias = (float*)(sm + 131072);

    int t = blockIdx.x;
    const __nv_bfloat16 *Ahi, *Alo, *Bhi, *Blo;
    const float* bias;
    float* Cmat;
    int M, N, tpr;
    if (t < s0.ntiles) {
        Ahi = s0.Ahi; Alo = s0.Alo; Bhi = s0.Bhi; Blo = s0.Blo;
        bias = s0.bias; Cmat = s0.C; M = s0.M; N = s0.N; tpr = s0.tilesPerRow;
    } else {
        t -= s0.ntiles;
        Ahi = s1.Ahi; Alo = s1.Alo; Bhi = s1.Bhi; Blo = s1.Blo;
        bias = s1.bias; Cmat = s1.C; M = s1.M; N = s1.N; tpr = s1.tilesPerRow;
    }
    const int bm = (t / tpr) * 128;
    const int bn = (t % tpr) * 128;

    const int tid  = threadIdx.x;
    const int lane = tid & 31;
    const int warp = tid >> 5;
    const int wm = (warp >> 2) * 64;
    const int wn = (warp & 3) * 32;

    if (tid < 128) pbias[tid] = bias[bn + tid];

    float acc[4][4][4];
#pragma unroll
    for (int i = 0; i < 4; i++)
#pragma unroll
        for (int j = 0; j < 4; j++)
#pragma unroll
            for (int k = 0; k < 4; k++) acc[i][j][k] = 0.f;

    const uint32_t mx = (uint32_t)((lane & 7) << 4);
    uint32_t aRow[4], bRow[2];
#pragma unroll
    for (int mi = 0; mi < 4; mi++)
        aRow[mi] = (uint32_t)((wm + mi * 16 + (lane & 15)) * 128);
    const uint32_t colA = (uint32_t)((lane >> 4) * 16);
#pragma unroll
    for (int nj2 = 0; nj2 < 2; nj2++)
        bRow[nj2] = (uint32_t)((wn + nj2 * 16 + (lane & 7) + ((lane >> 4) & 1) * 8) * 128);
    const uint32_t colB = (uint32_t)(((lane >> 3) & 1) * 16);

    auto stage_load = [&](int buf, int s) {
        const uint32_t bo = su + (uint32_t)buf * 65536u;
        const int ks2 = s * 128;
#pragma unroll
        for (int it = 0; it < 4; it++) {
            const int chunk = it * 256 + tid;
            const int r = chunk >> 3, c = chunk & 7;
            const uint32_t doff = (uint32_t)(r * 128) + (uint32_t)((c * 16) ^ ((r & 7) << 4));
            const int grow = bm + r;
            const uint32_t sza = (grow < M) ? 16u : 0u;
            const size_t aoff = (size_t)grow * 512 + ks2 + c * 16;
            cp_async16(bo + doff,         (const char*)Ahi + aoff, sza);
            cp_async16(bo + 16384 + doff, (const char*)Alo + aoff, sza);
            const size_t boff = (size_t)(bn + r) * 512 + ks2 + c * 16;
            cp_async16(bo + 32768 + doff, (const char*)Bhi + boff, 16u);
            cp_async16(bo + 49152 + doff, (const char*)Blo + boff, 16u);
        }
    };

    stage_load(0, 0);
    CP_COMMIT();

    for (int s = 0; s < 4; s++) {
        if (s < 3) { stage_load((s + 1) & 1, s + 1); CP_COMMIT(); CP_WAIT(1); }
        else       { CP_WAIT(0); }
        __syncthreads();

        const uint32_t bo = su + (uint32_t)(s & 1) * 65536u;
#pragma unroll
        for (int kk = 0; kk < 4; kk++) {
            uint32_t ah[4][4], al[4][4], bh[2][4], bl[2][4];
            const uint32_t ca = ((uint32_t)(kk * 32) + colA) ^ mx;
            const uint32_t cb = ((uint32_t)(kk * 32) + colB) ^ mx;
#pragma unroll
            for (int mi = 0; mi < 4; mi++) {
                const uint32_t ad = bo + aRow[mi] + ca;
                ldsm4(ah[mi], ad);
                ldsm4(al[mi], ad + 16384);
            }
#pragma unroll
            for (int nj2 = 0; nj2 < 2; nj2++) {
                const uint32_t bd = bo + 32768 + bRow[nj2] + cb;
                ldsm4(bh[nj2], bd);
                ldsm4(bl[nj2], bd + 16384);
            }
#pragma unroll
            for (int mi = 0; mi < 4; mi++) {
#pragma unroll
                for (int nj = 0; nj < 4; nj++) {
                    const uint32_t* bfh = &bh[nj >> 1][(nj & 1) * 2];
                    const uint32_t* bfl = &bl[nj >> 1][(nj & 1) * 2];
                    mma_bf16(acc[mi][nj], ah[mi], bfh);
                    mma_bf16(acc[mi][nj], ah[mi], bfl);
                    mma_bf16(acc[mi][nj], al[mi], bfh);
                }
            }
        }
        __syncthreads();
    }

    const int r0 = lane >> 2;
    const int c0 = (lane & 3) * 2;
#pragma unroll
    for (int mi = 0; mi < 4; mi++) {
        const int gm = bm + wm + mi * 16 + r0;
#pragma unroll
        for (int half = 0; half < 2; half++) {
            const int gmr = gm + half * 8;
            if (gmr < M) {
                float* op = Cmat + (size_t)gmr * N + bn;
#pragma unroll
                for (int nj = 0; nj < 4; nj++) {
                    const int cl = wn + nj * 8 + c0;
                    float2 o;
                    o.x = acc[mi][nj][half * 2 + 0] + pbias[cl];
                    o.y = acc[mi][nj][half * 2 + 1] + pbias[cl + 1];
                    *(float2*)(op + cl) = o;
                }
            }
        }
    }
}

// ---------------- sampling: softmax + paired bilinear gather -------------
__global__ void __launch_bounds__(256) sample_kernel(
    const float* __restrict__ ref)
{
    constexpr int LH[4]  = {100, 50, 25, 13};
    constexpr int LW[4]  = {150, 75, 38, 19};
    constexpr int LST[4] = {0, 15000, 18750, 19700};

    const int warp = (blockIdx.x * blockDim.x + threadIdx.x) >> 5;
    const int lane = threadIdx.x & 31;
    if (warp >= BB * NQ * NHD) return;

    const int h  = warp % NHD;
    const int bq = warp / NHD;
    const int b  = bq / NQ;
    const int sl = (lane >> 2) & 3;

    const float* qrow = g_qout + (size_t)bq * 384;

    // softmax over 16 logits, one per lane
    const float* logit = qrow + 256 + h * 16;
    float lg = (lane < 16) ? logit[lane] : -1e30f;
    float mxv = lg;
#pragma unroll
    for (int o = 8; o; o >>= 1) mxv = fmaxf(mxv, __shfl_xor_sync(0xffffffffu, mxv, o, 16));
    float ev = __expf(lg - mxv);
    float sum = ev;
#pragma unroll
    for (int o = 8; o; o >>= 1) sum += __shfl_xor_sync(0xffffffffu, sum, o, 16);
    const float aw = ev / sum;

    // per-lane sample coords (lanes 0..15 meaningful)
    const float2 off2 = ((const float2*)(qrow + h * 32))[lane & 15];
    const float2 rxy  = ((const float2*)(ref + (size_t)bq * 8))[sl];
    const float fW = (float)LW[sl], fH = (float)LH[sl];
    const float x = (rxy.x + off2.x / fW) * fW - 0.5f;
    const float y = (rxy.y + off2.y / fH) * fH - 0.5f;
    const float x0f = floorf(x), y0f = floorf(y);
    const float wx1 = x - x0f, wy1 = y - y0f;
    const int pk = (((int)y0f) << 16) | (((int)x0f) & 0xffff);
    // premultiply attention weight into the y-weights (owner side)
    const float wy0a_o = (1.f - wy1) * aw;
    const float wy1a_o = wy1 * aw;

    const int half = lane >> 4;
    const int chan = (lane & 15) * 2;
    float ax = 0.f, ay = 0.f;

#pragma unroll
    for (int l = 0; l < 4; l++) {
        const int W = LW[l], H = LH[l];
        const float* vbase = g_value
            + ((size_t)(b * S_TOT + LST[l]) * NHD + h) * DH + chan;
#pragma unroll
        for (int pp = 0; pp < 2; pp++) {
            const int sp  = l * 2 + pp;
            const int src = sp * 2 + half;
            const int   bpk  = __shfl_sync(0xffffffffu, pk,     src);
            const float bwx  = __shfl_sync(0xffffffffu, wx1,    src);
            const float wy0a = __shfl_sync(0xffffffffu, wy0a_o, src);
            const float wy1a = __shfl_sync(0xffffffffu, wy1a_o, src);
            const int bix = (int)(short)(bpk & 0xffff);
            const int biy = bpk >> 16;
            const float wx0 = 1.f - bwx;
            const bool xi0 = (unsigned)bix < (unsigned)W;
            const bool xi1 = (unsigned)(bix + 1) < (unsigned)W;
            const bool yi0 = (unsigned)biy < (unsigned)H;
            const bool yi1 = (unsigned)(biy + 1) < (unsigned)H;
            const float* pp0 = vbase + (ptrdiff_t)(biy * W + bix) * 256;
            if (yi0 && xi0) { const float2 v = *(const float2*)pp0;
                const float w = wx0 * wy0a; ax = fmaf(w, v.x, ax); ay = fmaf(w, v.y, ay); }
            if (yi0 && xi1) { const float2 v = *(const float2*)(pp0 + 256);
                const float w = bwx * wy0a; ax = fmaf(w, v.x, ax); ay = fmaf(w, v.y, ay); }
            if (yi1 && xi0) { const float2 v = *(const float2*)(pp0 + W * 256);
                const float w = wx0 * wy1a; ax = fmaf(w, v.x, ax); ay = fmaf(w, v.y, ay); }
            if (yi1 && xi1) { const float2 v = *(const float2*)(pp0 + W * 256 + 256);
                const float w = bwx * wy1a; ax = fmaf(w, v.x, ax); ay = fmaf(w, v.y, ay); }
        }
    }
    ax += __shfl_xor_sync(0xffffffffu, ax, 16);
    ay += __shfl_xor_sync(0xffffffffu, ay, 16);

    if (lane < 16) {
        __nv_bfloat16 hx = __float2bfloat16(ax);
        __nv_bfloat16 hy = __float2bfloat16(ay);
        __nv_bfloat16 lx = __float2bfloat16(ax - __bfloat162float(hx));
        __nv_bfloat16 ly = __float2bfloat16(ay - __bfloat162float(hy));
        const size_t idx = ((size_t)(bq * NHD + h) * DH + chan) >> 1;
        ((uint32_t*)g_s_hi)[idx] = (uint32_t)__bfloat16_as_ushort(hx) | ((uint32_t)__bfloat16_as_ushort(hy) << 16);
        ((uint32_t*)g_s_lo)[idx] = (uint32_t)__bfloat16_as_ushort(lx) | ((uint32_t)__bfloat16_as_ushort(ly) << 16);
    }
}

// ---------------- launch ----------------
#define GEMM_SMEM_BYTES 133120

extern "C" void kernel_launch(void* const* d_in, const int* in_sizes, int n_in,
                              void* d_out, int out_size)
{
    (void)in_sizes; (void)n_in; (void)out_size;
    const float* query  = (const float*)d_in[0];
    const float* vlv    = (const float*)d_in[1];
    const float* refpts = (const float*)d_in[2];
    const float* W_off  = (const float*)d_in[4];
    const float* b_off  = (const float*)d_in[5];
    const float* W_attn = (const float*)d_in[6];
    const float* b_attn = (const float*)d_in[7];
    const float* W_val  = (const float*)d_in[8];
    const float* b_val  = (const float*)d_in[9];
    const float* W_out  = (const float*)d_in[10];
    const float* b_out  = (const float*)d_in[11];
    float* out = (float*)d_out;

    cudaFuncSetAttribute(gemm_tc2_kernel,
                         cudaFuncAttributeMaxDynamicSharedMemorySize, GEMM_SMEM_BYTES);

    float *p_value, *p_qout, *p_qb;
    __nv_bfloat16 *p_vhi, *p_vlo, *p_qhi, *p_qlo, *p_shi, *p_slo, *p_whi, *p_wlo;
    cudaGetSymbolAddress((void**)&p_value, g_value);
    cudaGetSymbolAddress((void**)&p_qout,  g_qout);
    cudaGetSymbolAddress((void**)&p_qb,    g_qb);
    cudaGetSymbolAddress((void**)&p_vhi,   g_v_hi);
    cudaGetSymbolAddress((void**)&p_vlo,   g_v_lo);
    cudaGetSymbolAddress((void**)&p_qhi,   g_q_hi);
    cudaGetSymbolAddress((void**)&p_qlo,   g_q_lo);
    cudaGetSymbolAddress((void**)&p_shi,   g_s_hi);
    cudaGetSymbolAddress((void**)&p_slo,   g_s_lo);
    cudaGetSymbolAddress((void**)&p_whi,   g_w_hi);
    cudaGetSymbolAddress((void**)&p_wlo,   g_w_lo);

    __nv_bfloat16 *wv_hi = p_whi,           *wv_lo = p_wlo;
    __nv_bfloat16 *qw_hi = p_whi + 65536,   *qw_lo = p_wlo + 65536;
    __nv_bfloat16 *wu_hi = p_whi + 163840,  *wu_lo = p_wlo + 163840;

    // ---- 1. all conversions in one launch ----
    {
        ConvArgs ca;
        ca.vlv = vlv; ca.query = query;
        ca.w_val = W_val; ca.w_off = W_off; ca.w_attn = W_attn; ca.w_out = W_out;
        ca.b_off = b_off; ca.b_attn = b_attn;
        convert_all_kernel<<<NB_TOT, 256>>>(ca);
    }

    // ---- 2. value GEMM + q GEMM in one grid ----
    {
        GemmSeg sv, sq;
        sv.Ahi = p_vhi; sv.Alo = p_vlo; sv.Bhi = wv_hi; sv.Blo = wv_lo;
        sv.bias = b_val; sv.C = p_value; sv.M = MV; sv.N = 256;
        sv.tilesPerRow = 2; sv.ntiles = ((MV + 127) / 128) * 2;      // 1248
        sq.Ahi = p_qhi; sq.Alo = p_qlo; sq.Bhi = qw_hi; sq.Blo = qw_lo;
        sq.bias = p_qb; sq.C = p_qout; sq.M = MQ; sq.N = 384;
        sq.tilesPerRow = 3; sq.ntiles = (MQ / 128) * 3;              // 750
        gemm_tc2_kernel<<<sv.ntiles + sq.ntiles, 256, GEMM_SMEM_BYTES>>>(sv, sq);
    }

    // ---- 3. sampling ----
    {
        const int nwarp = BB * NQ * NHD;
        sample_kernel<<<(nwarp * 32 + 255) / 256, 256>>>(refpts);
    }

    // ---- 4. output GEMM ----
    {
        GemmSeg so, dummy;
        so.Ahi = p_shi; so.Alo = p_slo; so.Bhi = wu_hi; so.Blo = wu_lo;
        so.bias = b_out; so.C = out; so.M = MQ; so.N = 256;
        so.tilesPerRow = 2; so.ntiles = (MQ / 128) * 2;              // 500
        dummy = so; dummy.ntiles = 0;
        gemm_tc2_kernel<<<so.ntiles, 256, GEMM_SMEM_BYTES>>>(so, dummy);
    }
}

// round 8
// speedup vs baseline: 2.8934x; 1.0590x over previous
#include <cuda_runtime.h>
#include <cuda_bf16.h>
#include <cstdint>
#include <math.h>

// ---------------- problem constants ----------------
#define BB   4
#define NQ   8000
#define CC   256
#define NHD  8
#define NLV  4
#define NPT  4
#define DH   32
#define S_TOT 19947

#define MV (BB * S_TOT)   // 79788
#define MQ (BB * NQ)      // 32000

// ---------------- scratch ----------------
__device__ float g_value[(size_t)MV * CC];
__device__ float g_qout [(size_t)MQ * 384];
__device__ __nv_bfloat16 g_v_hi [(size_t)MV * CC];
__device__ __nv_bfloat16 g_v_lo [(size_t)MV * CC];
__device__ __nv_bfloat16 g_q_hi [(size_t)MQ * CC];
__device__ __nv_bfloat16 g_q_lo [(size_t)MQ * CC];
__device__ __nv_bfloat16 g_s_hi [(size_t)MQ * CC];
__device__ __nv_bfloat16 g_s_lo [(size_t)MQ * CC];
__device__ __nv_bfloat16 g_w_hi [65536 + 98304 + 65536];
__device__ __nv_bfloat16 g_w_lo [65536 + 98304 + 65536];
__device__ float g_qb[384];

// ---------------- helpers ----------------
__device__ __forceinline__ uint32_t smem_u32(const void* p) {
    uint32_t a;
    asm("{ .reg .u64 t; cvta.to.shared.u64 t, %1; cvt.u32.u64 %0, t; }" : "=r"(a) : "l"(p));
    return a;
}
__device__ __forceinline__ void ldsm4(uint32_t* r, uint32_t addr) {
    asm volatile("ldmatrix.sync.aligned.m8n8.x4.shared.b16 {%0,%1,%2,%3}, [%4];"
        : "=r"(r[0]), "=r"(r[1]), "=r"(r[2]), "=r"(r[3]) : "r"(addr));
}
__device__ __forceinline__ void mma_bf16(float* c, const uint32_t* a, const uint32_t* b) {
    asm volatile(
        "mma.sync.aligned.m16n8k16.row.col.f32.bf16.bf16.f32 "
        "{%0,%1,%2,%3}, {%4,%5,%6,%7}, {%8,%9}, {%0,%1,%2,%3};"
        : "+f"(c[0]), "+f"(c[1]), "+f"(c[2]), "+f"(c[3])
        : "r"(a[0]), "r"(a[1]), "r"(a[2]), "r"(a[3]), "r"(b[0]), "r"(b[1]));
}
__device__ __forceinline__ void cp_async16(uint32_t dst, const void* src, uint32_t sz) {
    asm volatile("cp.async.cg.shared.global [%0], [%1], 16, %2;"
        :: "r"(dst), "l"(src), "r"(sz) : "memory");
}
#define CP_COMMIT() asm volatile("cp.async.commit_group;" ::: "memory")
#define CP_WAIT(n)  asm volatile("cp.async.wait_group %0;" :: "n"(n) : "memory")

// ---------------- mega conversion kernel -------------------------------
#define NB_V  (MV / 4)
#define NB_Q  (MQ / 4)
#define NB_WV 64
#define NB_WO 64
#define NB_WA 32
#define NB_WU 64
#define NB_TOT (NB_V + NB_Q + NB_WV + NB_WO + NB_WA + NB_WU + 1)

struct ConvArgs {
    const float *vlv, *query, *w_val, *w_off, *w_attn, *w_out, *b_off, *b_attn;
};

__global__ void __launch_bounds__(256) convert_all_kernel(ConvArgs a)
{
    const int blk = blockIdx.x;
    const int tid = threadIdx.x;

    const float* src;
    uint2 *hi, *lo;
    int rel;

    if (blk < NB_V) {
        src = a.vlv; hi = (uint2*)g_v_hi; lo = (uint2*)g_v_lo; rel = blk;
    } else if (blk < NB_V + NB_Q) {
        src = a.query; hi = (uint2*)g_q_hi; lo = (uint2*)g_q_lo; rel = blk - NB_V;
    } else if (blk < NB_V + NB_Q + NB_WV) {
        src = a.w_val; hi = (uint2*)g_w_hi; lo = (uint2*)g_w_lo; rel = blk - (NB_V + NB_Q);
    } else if (blk < NB_V + NB_Q + NB_WV + NB_WO) {
        src = a.w_off; hi = (uint2*)(g_w_hi + 65536); lo = (uint2*)(g_w_lo + 65536);
        rel = blk - (NB_V + NB_Q + NB_WV);
    } else if (blk < NB_V + NB_Q + NB_WV + NB_WO + NB_WA) {
        src = a.w_attn; hi = (uint2*)(g_w_hi + 131072); lo = (uint2*)(g_w_lo + 131072);
        rel = blk - (NB_V + NB_Q + NB_WV + NB_WO);
    } else if (blk < NB_V + NB_Q + NB_WV + NB_WO + NB_WA + NB_WU) {
        src = a.w_out; hi = (uint2*)(g_w_hi + 163840); lo = (uint2*)(g_w_lo + 163840);
        rel = blk - (NB_V + NB_Q + NB_WV + NB_WO + NB_WA);
    } else {
        for (int i = tid; i < 384; i += 256)
            g_qb[i] = (i < 256) ? a.b_off[i] : a.b_attn[i - 256];
        return;
    }

    const int i = rel * 256 + tid;
    const float4 v = ((const float4*)src)[i];
    __nv_bfloat16 h0 = __float2bfloat16(v.x), h1 = __float2bfloat16(v.y);
    __nv_bfloat16 h2 = __float2bfloat16(v.z), h3 = __float2bfloat16(v.w);
    __nv_bfloat16 l0 = __float2bfloat16(v.x - __bfloat162float(h0));
    __nv_bfloat16 l1 = __float2bfloat16(v.y - __bfloat162float(h1));
    __nv_bfloat16 l2 = __float2bfloat16(v.z - __bfloat162float(h2));
    __nv_bfloat16 l3 = __float2bfloat16(v.w - __bfloat162float(h3));
    uint2 hp, lp;
    hp.x = (uint32_t)__bfloat16_as_ushort(h0) | ((uint32_t)__bfloat16_as_ushort(h1) << 16);
    hp.y = (uint32_t)__bfloat16_as_ushort(h2) | ((uint32_t)__bfloat16_as_ushort(h3) << 16);
    lp.x = (uint32_t)__bfloat16_as_ushort(l0) | ((uint32_t)__bfloat16_as_ushort(l1) << 16);
    lp.y = (uint32_t)__bfloat16_as_ushort(l2) | ((uint32_t)__bfloat16_as_ushort(l3) << 16);
    hi[i] = hp; lo[i] = lp;
}

// ============ HMMA GEMM: 64KB smem (half-row ping-pong), 2 CTAs/SM ============
struct GemmSeg {
    const __nv_bfloat16 *Ahi, *Alo, *Bhi, *Blo;
    const float* bias;
    float* C;
    int M, N, ntiles, tilesPerRow;
};

__global__ void __launch_bounds__(256, 2) gemm_tc2_kernel(GemmSeg s0, GemmSeg s1)
{
    extern __shared__ char smraw[];
    char* sm = (char*)(((uintptr_t)smraw + 1023) & ~(uintptr_t)1023);
    const uint32_t su = smem_u32(sm);
    float* pbias = (float*)(sm + 65536);

    int t = blockIdx.x;
    const __nv_bfloat16 *Ahi, *Alo, *Bhi, *Blo;
    const float* bias;
    float* Cmat;
    int M, N, tpr;
    if (t < s0.ntiles) {
        Ahi = s0.Ahi; Alo = s0.Alo; Bhi = s0.Bhi; Blo = s0.Blo;
        bias = s0.bias; Cmat = s0.C; M = s0.M; N = s0.N; tpr = s0.tilesPerRow;
    } else {
        t -= s0.ntiles;
        Ahi = s1.Ahi; Alo = s1.Alo; Bhi = s1.Bhi; Blo = s1.Blo;
        bias = s1.bias; Cmat = s1.C; M = s1.M; N = s1.N; tpr = s1.tilesPerRow;
    }
    const int bm = (t / tpr) * 128;
    const int bn = (t % tpr) * 128;

    const int tid  = threadIdx.x;
    const int lane = tid & 31;
    const int warp = tid >> 5;
    const int wm = (warp >> 2) * 64;
    const int wn = (warp & 3) * 32;

    if (tid < 128) pbias[tid] = bias[bn + tid];

    float acc[4][4][4];
#pragma unroll
    for (int i = 0; i < 4; i++)
#pragma unroll
        for (int j = 0; j < 4; j++)
#pragma unroll
            for (int k = 0; k < 4; k++) acc[i][j][k] = 0.f;

    const uint32_t mx = (uint32_t)((lane & 7) << 4);
    uint32_t aRow[4], bRow[2];
#pragma unroll
    for (int mi = 0; mi < 4; mi++)
        aRow[mi] = (uint32_t)((wm + mi * 16 + (lane & 15)) * 128);
    const uint32_t colA = (uint32_t)((lane >> 4) * 16);
#pragma unroll
    for (int nj2 = 0; nj2 < 2; nj2++)
        bRow[nj2] = (uint32_t)((wn + nj2 * 16 + (lane & 7) + ((lane >> 4) & 1) * 8) * 128);
    const uint32_t colB = (uint32_t)(((lane >> 3) & 1) * 16);

    auto load_half = [&](int hs) {
        const int hb = (hs & 1) * 64;
        const int ksrc = hs * 64;
#pragma unroll
        for (int pl = 0; pl < 4; pl++) {
            const __nv_bfloat16* gsrc = (pl == 0) ? Ahi : (pl == 1) ? Alo : (pl == 2) ? Bhi : Blo;
            const bool isA = (pl < 2);
            const uint32_t pbase = su + (uint32_t)pl * 16384u;
#pragma unroll
            for (int it = 0; it < 2; it++) {
                const int idx = it * 256 + tid;
                const int r = idx >> 2;
                const int c = idx & 3;
                const uint32_t doff = (uint32_t)(r * 128)
                    + (uint32_t)((hb + c * 16) ^ ((r & 7) << 4));
                const int grow = (isA ? bm : bn) + r;
                const uint32_t sz = (isA && grow >= M) ? 0u : 16u;
                const size_t soff = (size_t)grow * 512 + ksrc + c * 16;
                cp_async16(pbase + doff, (const char*)gsrc + soff, sz);
            }
        }
    };

    load_half(0); CP_COMMIT();
    load_half(1); CP_COMMIT();

    for (int hs = 0; hs < 8; hs++) {
        if (hs < 7) CP_WAIT(1); else CP_WAIT(0);
        __syncthreads();

        const uint32_t hb = (uint32_t)((hs & 1) * 64);
#pragma unroll
        for (int kk = 0; kk < 2; kk++) {
            uint32_t ah[4][4], al[4][4], bh[2][4], bl[2][4];
            const uint32_t ca = (hb + (uint32_t)(kk * 32) + colA) ^ mx;
            const uint32_t cb = (hb + (uint32_t)(kk * 32) + colB) ^ mx;
#pragma unroll
            for (int mi = 0; mi < 4; mi++) {
                const uint32_t ad = su + aRow[mi] + ca;
                ldsm4(ah[mi], ad);
                ldsm4(al[mi], ad + 16384);
            }
#pragma unroll
            for (int nj2 = 0; nj2 < 2; nj2++) {
                const uint32_t bd = su + 32768 + bRow[nj2] + cb;
                ldsm4(bh[nj2], bd);
                ldsm4(bl[nj2], bd + 16384);
            }
#pragma unroll
            for (int mi = 0; mi < 4; mi++) {
#pragma unroll
                for (int nj = 0; nj < 4; nj++) {
                    const uint32_t* bfh = &bh[nj >> 1][(nj & 1) * 2];
                    const uint32_t* bfl = &bl[nj >> 1][(nj & 1) * 2];
                    mma_bf16(acc[mi][nj], ah[mi], bfh);
                    mma_bf16(acc[mi][nj], ah[mi], bfl);
                    mma_bf16(acc[mi][nj], al[mi], bfh);
                }
            }
        }
        __syncthreads();
        if (hs < 6) { load_half(hs + 2); CP_COMMIT(); }
    }

    const int r0 = lane >> 2;
    const int c0 = (lane & 3) * 2;
#pragma unroll
    for (int mi = 0; mi < 4; mi++) {
        const int gm = bm + wm + mi * 16 + r0;
#pragma unroll
        for (int half = 0; half < 2; half++) {
            const int gmr = gm + half * 8;
            if (gmr < M) {
                float* op = Cmat + (size_t)gmr * N + bn;
#pragma unroll
                for (int nj = 0; nj < 4; nj++) {
                    const int cl = wn + nj * 8 + c0;
                    float2 o;
                    o.x = acc[mi][nj][half * 2 + 0] + pbias[cl];
                    o.y = acc[mi][nj][half * 2 + 1] + pbias[cl + 1];
                    *(float2*)(op + cl) = o;
                }
            }
        }
    }
}

// ---------------- sampling: softmax + paired bilinear gather -------------
__global__ void __launch_bounds__(256) sample_kernel(
    const float* __restrict__ ref)
{
    constexpr int LH[4]  = {100, 50, 25, 13};
    constexpr int LW[4]  = {150, 75, 38, 19};
    constexpr int LST[4] = {0, 15000, 18750, 19700};

    const int warp = (blockIdx.x * blockDim.x + threadIdx.x) >> 5;
    const int lane = threadIdx.x & 31;
    if (warp >= BB * NQ * NHD) return;

    const int h  = warp % NHD;
    const int bq = warp / NHD;
    const int b  = bq / NQ;
    const int sl = (lane >> 2) & 3;

    const float* qrow = g_qout + (size_t)bq * 384;

    const float* logit = qrow + 256 + h * 16;
    float lg = (lane < 16) ? logit[lane] : -1e30f;
    float mxv = lg;
#pragma unroll
    for (int o = 8; o; o >>= 1) mxv = fmaxf(mxv, __shfl_xor_sync(0xffffffffu, mxv, o, 16));
    float ev = __expf(lg - mxv);
    float sum = ev;
#pragma unroll
    for (int o = 8; o; o >>= 1) sum += __shfl_xor_sync(0xffffffffu, sum, o, 16);
    const float aw = ev / sum;

    const float2 off2 = ((const float2*)(qrow + h * 32))[lane & 15];
    const float2 rxy  = ((const float2*)(ref + (size_t)bq * 8))[sl];
    const float fW = (float)LW[sl], fH = (float)LH[sl];
    const float x = (rxy.x + off2.x / fW) * fW - 0.5f;
    const float y = (rxy.y + off2.y / fH) * fH - 0.5f;
    const float x0f = floorf(x), y0f = floorf(y);
    const float wx1 = x - x0f, wy1 = y - y0f;
    const int pk = (((int)y0f) << 16) | (((int)x0f) & 0xffff);
    const float wy0a_o = (1.f - wy1) * aw;
    const float wy1a_o = wy1 * aw;

    const int half = lane >> 4;
    const int chan = (lane & 15) * 2;
    float ax = 0.f, ay = 0.f;

#pragma unroll
    for (int l = 0; l < 4; l++) {
        const int W = LW[l], H = LH[l];
        const float* vbase = g_value
            + ((size_t)(b * S_TOT + LST[l]) * NHD + h) * DH + chan;
#pragma unroll
        for (int pp = 0; pp < 2; pp++) {
            const int sp  = l * 2 + pp;
            const int src = sp * 2 + half;
            const int   bpk  = __shfl_sync(0xffffffffu, pk,     src);
            const float bwx  = __shfl_sync(0xffffffffu, wx1,    src);
            const float wy0a = __shfl_sync(0xffffffffu, wy0a_o, src);
            const float wy1a = __shfl_sync(0xffffffffu, wy1a_o, src);
            const int bix = (int)(short)(bpk & 0xffff);
            const int biy = bpk >> 16;
            const float wx0 = 1.f - bwx;
            const bool xi0 = (unsigned)bix < (unsigned)W;
            const bool xi1 = (unsigned)(bix + 1) < (unsigned)W;
            const bool yi0 = (unsigned)biy < (unsigned)H;
            const bool yi1 = (unsigned)(biy + 1) < (unsigned)H;
            const float* pp0 = vbase + (ptrdiff_t)(biy * W + bix) * 256;
            if (yi0 && xi0) { const float2 v = *(const float2*)pp0;
                const float w = wx0 * wy0a; ax = fmaf(w, v.x, ax); ay = fmaf(w, v.y, ay); }
            if (yi0 && xi1) { const float2 v = *(const float2*)(pp0 + 256);
                const float w = bwx * wy0a; ax = fmaf(w, v.x, ax); ay = fmaf(w, v.y, ay); }
            if (yi1 && xi0) { const float2 v = *(const float2*)(pp0 + W * 256);
                const float w = wx0 * wy1a; ax = fmaf(w, v.x, ax); ay = fmaf(w, v.y, ay); }
            if (yi1 && xi1) { const float2 v = *(const float2*)(pp0 + W * 256 + 256);
                const float w = bwx * wy1a; ax = fmaf(w, v.x, ax); ay = fmaf(w, v.y, ay); }
        }
    }
    ax += __shfl_xor_sync(0xffffffffu, ax, 16);
    ay += __shfl_xor_sync(0xffffffffu, ay, 16);

    if (lane < 16) {
        __nv_bfloat16 hx = __float2bfloat16(ax);
        __nv_bfloat16 hy = __float2bfloat16(ay);
        __nv_bfloat16 lx = __float2bfloat16(ax - __bfloat162float(hx));
        __nv_bfloat16 ly = __float2bfloat16(ay - __bfloat162float(hy));
        const size_t idx = ((size_t)(bq * NHD + h) * DH + chan) >> 1;
        ((uint32_t*)g_s_hi)[idx] = (uint32_t)__bfloat16_as_ushort(hx) | ((uint32_t)__bfloat16_as_ushort(hy) << 16);
        ((uint32_t*)g_s_lo)[idx] = (uint32_t)__bfloat16_as_ushort(lx) | ((uint32_t)__bfloat16_as_ushort(ly) << 16);
    }
}

// ---------------- launch ----------------
#define GEMM_SMEM_BYTES 67584

extern "C" void kernel_launch(void* const* d_in, const int* in_sizes, int n_in,
                              void* d_out, int out_size)
{
    (void)in_sizes; (void)n_in; (void)out_size;
    const float* query  = (const float*)d_in[0];
    const float* vlv    = (const float*)d_in[1];
    const float* refpts = (const float*)d_in[2];
    const float* W_off  = (const float*)d_in[4];
    const float* b_off  = (const float*)d_in[5];
    const float* W_attn = (const float*)d_in[6];
    const float* b_attn = (const float*)d_in[7];
    const float* W_val  = (const float*)d_in[8];
    const float* b_val  = (const float*)d_in[9];
    const float* W_out  = (const float*)d_in[10];
    const float* b_out  = (const float*)d_in[11];
    float* out = (float*)d_out;

    cudaFuncSetAttribute(gemm_tc2_kernel,
                         cudaFuncAttributeMaxDynamicSharedMemorySize, GEMM_SMEM_BYTES);

    float *p_value, *p_qout, *p_qb;
    __nv_bfloat16 *p_vhi, *p_vlo, *p_qhi, *p_qlo, *p_shi, *p_slo, *p_whi, *p_wlo;
    cudaGetSymbolAddress((void**)&p_value, g_value);
    cudaGetSymbolAddress((void**)&p_qout,  g_qout);
    cudaGetSymbolAddress((void**)&p_qb,    g_qb);
    cudaGetSymbolAddress((void**)&p_vhi,   g_v_hi);
    cudaGetSymbolAddress((void**)&p_vlo,   g_v_lo);
    cudaGetSymbolAddress((void**)&p_qhi,   g_q_hi);
    cudaGetSymbolAddress((void**)&p_qlo,   g_q_lo);
    cudaGetSymbolAddress((void**)&p_shi,   g_s_hi);
    cudaGetSymbolAddress((void**)&p_slo,   g_s_lo);
    cudaGetSymbolAddress((void**)&p_whi,   g_w_hi);
    cudaGetSymbolAddress((void**)&p_wlo,   g_w_lo);

    __nv_bfloat16 *wv_hi = p_whi,           *wv_lo = p_wlo;
    __nv_bfloat16 *qw_hi = p_whi + 65536,   *qw_lo = p_wlo + 65536;
    __nv_bfloat16 *wu_hi = p_whi + 163840,  *wu_lo = p_wlo + 163840;

    {
        ConvArgs ca;
        ca.vlv = vlv; ca.query = query;
        ca.w_val = W_val; ca.w_off = W_off; ca.w_attn = W_attn; ca.w_out = W_out;
        ca.b_off = b_off; ca.b_attn = b_attn;
        convert_all_kernel<<<NB_TOT, 256>>>(ca);
    }

    {
        GemmSeg sv, sq;
        sv.Ahi = p_vhi; sv.Alo = p_vlo; sv.Bhi = wv_hi; sv.Blo = wv_lo;
        sv.bias = b_val; sv.C = p_value; sv.M = MV; sv.N = 256;
        sv.tilesPerRow = 2; sv.ntiles = ((MV + 127) / 128) * 2;
        sq.Ahi = p_qhi; sq.Alo = p_qlo; sq.Bhi = qw_hi; sq.Blo = qw_lo;
        sq.bias = p_qb; sq.C = p_qout; sq.M = MQ; sq.N = 384;
        sq.tilesPerRow = 3; sq.ntiles = (MQ / 128) * 3;
        gemm_tc2_kernel<<<sv.ntiles + sq.ntiles, 256, GEMM_SMEM_BYTES>>>(sv, sq);
    }

    {
        const int nwarp = BB * NQ * NHD;
        sample_kernel<<<(nwarp * 32 + 255) / 256, 256>>>(refpts);
    }

    {
        GemmSeg so, dummy;
        so.Ahi = p_shi; so.Alo = p_slo; so.Bhi = wu_hi; so.Blo = wu_lo;
        so.bias = b_out; so.C = out; so.M = MQ; so.N = 256;
        so.tilesPerRow = 2; so.ntiles = (MQ / 128) * 2;
        dummy = so; dummy.ntiles = 0;
        gemm_tc2_kernel<<<so.ntiles, 256, GEMM_SMEM_BYTES>>>(so, dummy);
    }
}

// round 9
// speedup vs baseline: 2.9270x; 1.0116x over previous
#include <cuda_runtime.h>
#include <cuda_bf16.h>
#include <cstdint>
#include <math.h>

// ---------------- problem constants ----------------
#define BB   4
#define NQ   8000
#define CC   256
#define NHD  8
#define NLV  4
#define NPT  4
#define DH   32
#define S_TOT 19947

#define MV (BB * S_TOT)   // 79788
#define MQ (BB * NQ)      // 32000

// ---------------- scratch ----------------
__device__ float g_value[(size_t)MV * CC];
__device__ float g_qout [(size_t)MQ * 384];
__device__ __nv_bfloat16 g_v_hi [(size_t)MV * CC];
__device__ __nv_bfloat16 g_v_lo [(size_t)MV * CC];
__device__ __nv_bfloat16 g_q_hi [(size_t)MQ * CC];
__device__ __nv_bfloat16 g_q_lo [(size_t)MQ * CC];
__device__ __nv_bfloat16 g_s_hi [(size_t)MQ * CC];
__device__ __nv_bfloat16 g_s_lo [(size_t)MQ * CC];
__device__ __nv_bfloat16 g_w_hi [65536 + 98304 + 65536];
__device__ __nv_bfloat16 g_w_lo [65536 + 98304 + 65536];
__device__ float g_qb[384];

// ---------------- helpers ----------------
__device__ __forceinline__ uint32_t smem_u32(const void* p) {
    uint32_t a;
    asm("{ .reg .u64 t; cvta.to.shared.u64 t, %1; cvt.u32.u64 %0, t; }" : "=r"(a) : "l"(p));
    return a;
}
__device__ __forceinline__ void ldsm4(uint32_t* r, uint32_t addr) {
    asm volatile("ldmatrix.sync.aligned.m8n8.x4.shared.b16 {%0,%1,%2,%3}, [%4];"
        : "=r"(r[0]), "=r"(r[1]), "=r"(r[2]), "=r"(r[3]) : "r"(addr));
}
__device__ __forceinline__ void mma_bf16(float* c, const uint32_t* a, const uint32_t* b) {
    asm volatile(
        "mma.sync.aligned.m16n8k16.row.col.f32.bf16.bf16.f32 "
        "{%0,%1,%2,%3}, {%4,%5,%6,%7}, {%8,%9}, {%0,%1,%2,%3};"
        : "+f"(c[0]), "+f"(c[1]), "+f"(c[2]), "+f"(c[3])
        : "r"(a[0]), "r"(a[1]), "r"(a[2]), "r"(a[3]), "r"(b[0]), "r"(b[1]));
}
__device__ __forceinline__ void cp_async16(uint32_t dst, const void* src, uint32_t sz) {
    asm volatile("cp.async.cg.shared.global [%0], [%1], 16, %2;"
        :: "r"(dst), "l"(src), "r"(sz) : "memory");
}
#define CP_COMMIT() asm volatile("cp.async.commit_group;" ::: "memory")
#define CP_WAIT(n)  asm volatile("cp.async.wait_group %0;" :: "n"(n) : "memory")

// ---------------- mega conversion kernel -------------------------------
#define NB_V  (MV / 4)
#define NB_Q  (MQ / 4)
#define NB_WV 64
#define NB_WO 64
#define NB_WA 32
#define NB_WU 64
#define NB_TOT (NB_V + NB_Q + NB_WV + NB_WO + NB_WA + NB_WU + 1)

struct ConvArgs {
    const float *vlv, *query, *w_val, *w_off, *w_attn, *w_out, *b_off, *b_attn;
};

__global__ void __launch_bounds__(256) convert_all_kernel(ConvArgs a)
{
    const int blk = blockIdx.x;
    const int tid = threadIdx.x;

    const float* src;
    uint2 *hi, *lo;
    int rel;

    if (blk < NB_V) {
        src = a.vlv; hi = (uint2*)g_v_hi; lo = (uint2*)g_v_lo; rel = blk;
    } else if (blk < NB_V + NB_Q) {
        src = a.query; hi = (uint2*)g_q_hi; lo = (uint2*)g_q_lo; rel = blk - NB_V;
    } else if (blk < NB_V + NB_Q + NB_WV) {
        src = a.w_val; hi = (uint2*)g_w_hi; lo = (uint2*)g_w_lo; rel = blk - (NB_V + NB_Q);
    } else if (blk < NB_V + NB_Q + NB_WV + NB_WO) {
        src = a.w_off; hi = (uint2*)(g_w_hi + 65536); lo = (uint2*)(g_w_lo + 65536);
        rel = blk - (NB_V + NB_Q + NB_WV);
    } else if (blk < NB_V + NB_Q + NB_WV + NB_WO + NB_WA) {
        src = a.w_attn; hi = (uint2*)(g_w_hi + 131072); lo = (uint2*)(g_w_lo + 131072);
        rel = blk - (NB_V + NB_Q + NB_WV + NB_WO);
    } else if (blk < NB_V + NB_Q + NB_WV + NB_WO + NB_WA + NB_WU) {
        src = a.w_out; hi = (uint2*)(g_w_hi + 163840); lo = (uint2*)(g_w_lo + 163840);
        rel = blk - (NB_V + NB_Q + NB_WV + NB_WO + NB_WA);
    } else {
        for (int i = tid; i < 384; i += 256)
            g_qb[i] = (i < 256) ? a.b_off[i] : a.b_attn[i - 256];
        return;
    }

    const int i = rel * 256 + tid;
    const float4 v = ((const float4*)src)[i];
    __nv_bfloat16 h0 = __float2bfloat16(v.x), h1 = __float2bfloat16(v.y);
    __nv_bfloat16 h2 = __float2bfloat16(v.z), h3 = __float2bfloat16(v.w);
    __nv_bfloat16 l0 = __float2bfloat16(v.x - __bfloat162float(h0));
    __nv_bfloat16 l1 = __float2bfloat16(v.y - __bfloat162float(h1));
    __nv_bfloat16 l2 = __float2bfloat16(v.z - __bfloat162float(h2));
    __nv_bfloat16 l3 = __float2bfloat16(v.w - __bfloat162float(h3));
    uint2 hp, lp;
    hp.x = (uint32_t)__bfloat16_as_ushort(h0) | ((uint32_t)__bfloat16_as_ushort(h1) << 16);
    hp.y = (uint32_t)__bfloat16_as_ushort(h2) | ((uint32_t)__bfloat16_as_ushort(h3) << 16);
    lp.x = (uint32_t)__bfloat16_as_ushort(l0) | ((uint32_t)__bfloat16_as_ushort(l1) << 16);
    lp.y = (uint32_t)__bfloat16_as_ushort(l2) | ((uint32_t)__bfloat16_as_ushort(l3) << 16);
    hi[i] = hp; lo[i] = lp;
}

// ============ HMMA GEMM: 64KB smem, 2 CTAs/SM, term-major MMA order ============
struct GemmSeg {
    const __nv_bfloat16 *Ahi, *Alo, *Bhi, *Blo;
    const float* bias;
    float* C;
    int M, N, ntiles, tilesPerRow;
};

__global__ void __launch_bounds__(256, 2) gemm_tc2_kernel(GemmSeg s0, GemmSeg s1)
{
    extern __shared__ char smraw[];
    char* sm = (char*)(((uintptr_t)smraw + 1023) & ~(uintptr_t)1023);
    const uint32_t su = smem_u32(sm);
    float* pbias = (float*)(sm + 65536);

    int t = blockIdx.x;
    const __nv_bfloat16 *Ahi, *Alo, *Bhi, *Blo;
    const float* bias;
    float* Cmat;
    int M, N, tpr;
    if (t < s0.ntiles) {
        Ahi = s0.Ahi; Alo = s0.Alo; Bhi = s0.Bhi; Blo = s0.Blo;
        bias = s0.bias; Cmat = s0.C; M = s0.M; N = s0.N; tpr = s0.tilesPerRow;
    } else {
        t -= s0.ntiles;
        Ahi = s1.Ahi; Alo = s1.Alo; Bhi = s1.Bhi; Blo = s1.Blo;
        bias = s1.bias; Cmat = s1.C; M = s1.M; N = s1.N; tpr = s1.tilesPerRow;
    }
    const int bm = (t / tpr) * 128;
    const int bn = (t % tpr) * 128;

    const int tid  = threadIdx.x;
    const int lane = tid & 31;
    const int warp = tid >> 5;
    const int wm = (warp >> 2) * 64;
    const int wn = (warp & 3) * 32;

    if (tid < 128) pbias[tid] = bias[bn + tid];

    float acc[4][4][4];
#pragma unroll
    for (int i = 0; i < 4; i++)
#pragma unroll
        for (int j = 0; j < 4; j++)
#pragma unroll
            for (int k = 0; k < 4; k++) acc[i][j][k] = 0.f;

    const uint32_t mx = (uint32_t)((lane & 7) << 4);
    uint32_t aRow[4], bRow[2];
#pragma unroll
    for (int mi = 0; mi < 4; mi++)
        aRow[mi] = (uint32_t)((wm + mi * 16 + (lane & 15)) * 128);
    const uint32_t colA = (uint32_t)((lane >> 4) * 16);
#pragma unroll
    for (int nj2 = 0; nj2 < 2; nj2++)
        bRow[nj2] = (uint32_t)((wn + nj2 * 16 + (lane & 7) + ((lane >> 4) & 1) * 8) * 128);
    const uint32_t colB = (uint32_t)(((lane >> 3) & 1) * 16);

    auto load_half = [&](int hs) {
        const int hb = (hs & 1) * 64;
        const int ksrc = hs * 64;
#pragma unroll
        for (int pl = 0; pl < 4; pl++) {
            const __nv_bfloat16* gsrc = (pl == 0) ? Ahi : (pl == 1) ? Alo : (pl == 2) ? Bhi : Blo;
            const bool isA = (pl < 2);
            const uint32_t pbase = su + (uint32_t)pl * 16384u;
#pragma unroll
            for (int it = 0; it < 2; it++) {
                const int idx = it * 256 + tid;
                const int r = idx >> 2;
                const int c = idx & 3;
                const uint32_t doff = (uint32_t)(r * 128)
                    + (uint32_t)((hb + c * 16) ^ ((r & 7) << 4));
                const int grow = (isA ? bm : bn) + r;
                const uint32_t sz = (isA && grow >= M) ? 0u : 16u;
                const size_t soff = (size_t)grow * 512 + ksrc + c * 16;
                cp_async16(pbase + doff, (const char*)gsrc + soff, sz);
            }
        }
    };

    load_half(0); CP_COMMIT();
    load_half(1); CP_COMMIT();

    for (int hs = 0; hs < 8; hs++) {
        if (hs < 7) CP_WAIT(1); else CP_WAIT(0);
        __syncthreads();

        const uint32_t hb = (uint32_t)((hs & 1) * 64);
#pragma unroll
        for (int kk = 0; kk < 2; kk++) {
            uint32_t ah[4][4], al[4][4], bh[2][4], bl[2][4];
            const uint32_t ca = (hb + (uint32_t)(kk * 32) + colA) ^ mx;
            const uint32_t cb = (hb + (uint32_t)(kk * 32) + colB) ^ mx;
#pragma unroll
            for (int mi = 0; mi < 4; mi++) {
                const uint32_t ad = su + aRow[mi] + ca;
                ldsm4(ah[mi], ad);
                ldsm4(al[mi], ad + 16384);
            }
#pragma unroll
            for (int nj2 = 0; nj2 < 2; nj2++) {
                const uint32_t bd = su + 32768 + bRow[nj2] + cb;
                ldsm4(bh[nj2], bd);
                ldsm4(bl[nj2], bd + 16384);
            }
            // term-major: consecutive MMAs never share an accumulator (RAW dist = 16)
#pragma unroll
            for (int mi = 0; mi < 4; mi++)
#pragma unroll
                for (int nj = 0; nj < 4; nj++)
                    mma_bf16(acc[mi][nj], ah[mi], &bh[nj >> 1][(nj & 1) * 2]);
#pragma unroll
            for (int mi = 0; mi < 4; mi++)
#pragma unroll
                for (int nj = 0; nj < 4; nj++)
                    mma_bf16(acc[mi][nj], ah[mi], &bl[nj >> 1][(nj & 1) * 2]);
#pragma unroll
            for (int mi = 0; mi < 4; mi++)
#pragma unroll
                for (int nj = 0; nj < 4; nj++)
                    mma_bf16(acc[mi][nj], al[mi], &bh[nj >> 1][(nj & 1) * 2]);
        }
        __syncthreads();
        if (hs < 6) { load_half(hs + 2); CP_COMMIT(); }
    }

    const int r0 = lane >> 2;
    const int c0 = (lane & 3) * 2;
#pragma unroll
    for (int mi = 0; mi < 4; mi++) {
        const int gm = bm + wm + mi * 16 + r0;
#pragma unroll
        for (int half = 0; half < 2; half++) {
            const int gmr = gm + half * 8;
            if (gmr < M) {
                float* op = Cmat + (size_t)gmr * N + bn;
#pragma unroll
                for (int nj = 0; nj < 4; nj++) {
                    const int cl = wn + nj * 8 + c0;
                    float2 o;
                    o.x = acc[mi][nj][half * 2 + 0] + pbias[cl];
                    o.y = acc[mi][nj][half * 2 + 1] + pbias[cl + 1];
                    *(float2*)(op + cl) = o;
                }
            }
        }
    }
}

// ---------------- sampling: softmax + quad-channel bilinear gather -------
// one warp per (b,q,h). lanes 0..15 own one (level,point) sample's coords.
// gather: 4 samples (one level) per step; grp = lane>>3 picks sample,
// (lane&7)*4 picks the channel quad (float4 loads).
__global__ void __launch_bounds__(256) sample_kernel(
    const float* __restrict__ ref)
{
    constexpr int LH[4]  = {100, 50, 25, 13};
    constexpr int LW[4]  = {150, 75, 38, 19};
    constexpr int LST[4] = {0, 15000, 18750, 19700};

    const int warp = (blockIdx.x * blockDim.x + threadIdx.x) >> 5;
    const int lane = threadIdx.x & 31;
    if (warp >= BB * NQ * NHD) return;

    const int h  = warp % NHD;
    const int bq = warp / NHD;
    const int b  = bq / NQ;
    const int sl = (lane >> 2) & 3;

    const float* qrow = g_qout + (size_t)bq * 384;

    // softmax over 16 logits, one per lane
    const float* logit = qrow + 256 + h * 16;
    float lg = (lane < 16) ? logit[lane] : -1e30f;
    float mxv = lg;
#pragma unroll
    for (int o = 8; o; o >>= 1) mxv = fmaxf(mxv, __shfl_xor_sync(0xffffffffu, mxv, o, 16));
    float ev = __expf(lg - mxv);
    float sum = ev;
#pragma unroll
    for (int o = 8; o; o >>= 1) sum += __shfl_xor_sync(0xffffffffu, sum, o, 16);
    const float aw = ev / sum;

    // per-lane sample coords (lanes 0..15 meaningful)
    const float2 off2 = ((const float2*)(qrow + h * 32))[lane & 15];
    const float2 rxy  = ((const float2*)(ref + (size_t)bq * 8))[sl];
    const float fW = (float)LW[sl], fH = (float)LH[sl];
    const float x = (rxy.x + off2.x / fW) * fW - 0.5f;
    const float y = (rxy.y + off2.y / fH) * fH - 0.5f;
    const float x0f = floorf(x), y0f = floorf(y);
    const float wx1 = x - x0f, wy1 = y - y0f;
    const int pk = (((int)y0f) << 16) | (((int)x0f) & 0xffff);
    const float wy0a_o = (1.f - wy1) * aw;
    const float wy1a_o = wy1 * aw;

    const int grp  = lane >> 3;          // sample-in-level (0..3)
    const int chan = (lane & 7) * 4;     // channel quad
    float a0 = 0.f, a1 = 0.f, a2 = 0.f, a3 = 0.f;

#pragma unroll
    for (int l = 0; l < 4; l++) {
        const int W = LW[l], H = LH[l];
        const float* vbase = g_value
            + ((size_t)(b * S_TOT + LST[l]) * NHD + h) * DH + chan;
        const int src = l * 4 + grp;     // lane owning this sample's coords
        const int   bpk  = __shfl_sync(0xffffffffu, pk,     src);
        const float bwx  = __shfl_sync(0xffffffffu, wx1,    src);
        const float wy0a = __shfl_sync(0xffffffffu, wy0a_o, src);
        const float wy1a = __shfl_sync(0xffffffffu, wy1a_o, src);
        const int bix = (int)(short)(bpk & 0xffff);
        const int biy = bpk >> 16;
        const float wx0 = 1.f - bwx;
        const bool xi0 = (unsigned)bix < (unsigned)W;
        const bool xi1 = (unsigned)(bix + 1) < (unsigned)W;
        const bool yi0 = (unsigned)biy < (unsigned)H;
        const bool yi1 = (unsigned)(biy + 1) < (unsigned)H;
        const float* pp0 = vbase + (ptrdiff_t)(biy * W + bix) * 256;
        if (yi0 && xi0) { const float4 v = *(const float4*)pp0;
            const float w = wx0 * wy0a;
            a0 = fmaf(w, v.x, a0); a1 = fmaf(w, v.y, a1);
            a2 = fmaf(w, v.z, a2); a3 = fmaf(w, v.w, a3); }
        if (yi0 && xi1) { const float4 v = *(const float4*)(pp0 + 256);
            const float w = bwx * wy0a;
            a0 = fmaf(w, v.x, a0); a1 = fmaf(w, v.y, a1);
            a2 = fmaf(w, v.z, a2); a3 = fmaf(w, v.w, a3); }
        if (yi1 && xi0) { const float4 v = *(const float4*)(pp0 + W * 256);
            const float w = wx0 * wy1a;
            a0 = fmaf(w, v.x, a0); a1 = fmaf(w, v.y, a1);
            a2 = fmaf(w, v.z, a2); a3 = fmaf(w, v.w, a3); }
        if (yi1 && xi1) { const float4 v = *(const float4*)(pp0 + W * 256 + 256);
            const float w = bwx * wy1a;
            a0 = fmaf(w, v.x, a0); a1 = fmaf(w, v.y, a1);
            a2 = fmaf(w, v.z, a2); a3 = fmaf(w, v.w, a3); }
    }
    // sum the 4 sample-groups (lanes differing in bits 3,4 share a channel quad)
#pragma unroll
    for (int o = 8; o <= 16; o <<= 1) {
        a0 += __shfl_xor_sync(0xffffffffu, a0, o);
        a1 += __shfl_xor_sync(0xffffffffu, a1, o);
        a2 += __shfl_xor_sync(0xffffffffu, a2, o);
        a3 += __shfl_xor_sync(0xffffffffu, a3, o);
    }

    if (lane < 8) {
        __nv_bfloat16 h0 = __float2bfloat16(a0), h1 = __float2bfloat16(a1);
        __nv_bfloat16 h2 = __float2bfloat16(a2), h3 = __float2bfloat16(a3);
        __nv_bfloat16 l0 = __float2bfloat16(a0 - __bfloat162float(h0));
        __nv_bfloat16 l1 = __float2bfloat16(a1 - __bfloat162float(h1));
        __nv_bfloat16 l2 = __float2bfloat16(a2 - __bfloat162float(h2));
        __nv_bfloat16 l3 = __float2bfloat16(a3 - __bfloat162float(h3));
        uint2 hp, lp;
        hp.x = (uint32_t)__bfloat16_as_ushort(h0) | ((uint32_t)__bfloat16_as_ushort(h1) << 16);
        hp.y = (uint32_t)__bfloat16_as_ushort(h2) | ((uint32_t)__bfloat16_as_ushort(h3) << 16);
        lp.x = (uint32_t)__bfloat16_as_ushort(l0) | ((uint32_t)__bfloat16_as_ushort(l1) << 16);
        lp.y = (uint32_t)__bfloat16_as_ushort(l2) | ((uint32_t)__bfloat16_as_ushort(l3) << 16);
        const size_t q2 = (size_t)(bq * NHD + h) * 8 + (lane & 7);  // uint2 index
        ((uint2*)g_s_hi)[q2] = hp;
        ((uint2*)g_s_lo)[q2] = lp;
    }
}

// ---------------- launch ----------------
#define GEMM_SMEM_BYTES 67584

extern "C" void kernel_launch(void* const* d_in, const int* in_sizes, int n_in,
                              void* d_out, int out_size)
{
    (void)in_sizes; (void)n_in; (void)out_size;
    const float* query  = (const float*)d_in[0];
    const float* vlv    = (const float*)d_in[1];
    const float* refpts = (const float*)d_in[2];
    const float* W_off  = (const float*)d_in[4];
    const float* b_off  = (const float*)d_in[5];
    const float* W_attn = (const float*)d_in[6];
    const float* b_attn = (const float*)d_in[7];
    const float* W_val  = (const float*)d_in[8];
    const float* b_val  = (const float*)d_in[9];
    const float* W_out  = (const float*)d_in[10];
    const float* b_out  = (const float*)d_in[11];
    float* out = (float*)d_out;

    cudaFuncSetAttribute(gemm_tc2_kernel,
                         cudaFuncAttributeMaxDynamicSharedMemorySize, GEMM_SMEM_BYTES);

    float *p_value, *p_qout, *p_qb;
    __nv_bfloat16 *p_vhi, *p_vlo, *p_qhi, *p_qlo, *p_shi, *p_slo, *p_whi, *p_wlo;
    cudaGetSymbolAddress((void**)&p_value, g_value);
    cudaGetSymbolAddress((void**)&p_qout,  g_qout);
    cudaGetSymbolAddress((void**)&p_qb,    g_qb);
    cudaGetSymbolAddress((void**)&p_vhi,   g_v_hi);
    cudaGetSymbolAddress((void**)&p_vlo,   g_v_lo);
    cudaGetSymbolAddress((void**)&p_qhi,   g_q_hi);
    cudaGetSymbolAddress((void**)&p_qlo,   g_q_lo);
    cudaGetSymbolAddress((void**)&p_shi,   g_s_hi);
    cudaGetSymbolAddress((void**)&p_slo,   g_s_lo);
    cudaGetSymbolAddress((void**)&p_whi,   g_w_hi);
    cudaGetSymbolAddress((void**)&p_wlo,   g_w_lo);

    __nv_bfloat16 *wv_hi = p_whi,           *wv_lo = p_wlo;
    __nv_bfloat16 *qw_hi = p_whi + 65536,   *qw_lo = p_wlo + 65536;
    __nv_bfloat16 *wu_hi = p_whi + 163840,  *wu_lo = p_wlo + 163840;

    {
        ConvArgs ca;
        ca.vlv = vlv; ca.query = query;
        ca.w_val = W_val; ca.w_off = W_off; ca.w_attn = W_attn; ca.w_out = W_out;
        ca.b_off = b_off; ca.b_attn = b_attn;
        convert_all_kernel<<<NB_TOT, 256>>>(ca);
    }

    {
        GemmSeg sv, sq;
        sv.Ahi = p_vhi; sv.Alo = p_vlo; sv.Bhi = wv_hi; sv.Blo = wv_lo;
        sv.bias = b_val; sv.C = p_value; sv.M = MV; sv.N = 256;
        sv.tilesPerRow = 2; sv.ntiles = ((MV + 127) / 128) * 2;
        sq.Ahi = p_qhi; sq.Alo = p_qlo; sq.Bhi = qw_hi; sq.Blo = qw_lo;
        sq.bias = p_qb; sq.C = p_qout; sq.M = MQ; sq.N = 384;
        sq.tilesPerRow = 3; sq.ntiles = (MQ / 128) * 3;
        gemm_tc2_kernel<<<sv.ntiles + sq.ntiles, 256, GEMM_SMEM_BYTES>>>(sv, sq);
    }

    {
        const int nwarp = BB * NQ * NHD;
        sample_kernel<<<(nwarp * 32 + 255) / 256, 256>>>(refpts);
    }

    {
        GemmSeg so, dummy;
        so.Ahi = p_shi; so.Alo = p_slo; so.Bhi = wu_hi; so.Blo = wu_lo;
        so.bias = b_out; so.C = out; so.M = MQ; so.N = 256;
        so.tilesPerRow = 2; so.ntiles = (MQ / 128) * 2;
        dummy = so; dummy.ntiles = 0;
        gemm_tc2_kernel<<<so.ntiles, 256, GEMM_SMEM_BYTES>>>(so, dummy);
    }
}

// round 10
// speedup vs baseline: 2.9999x; 1.0249x over previous
#include <cuda_runtime.h>
#include <cuda_bf16.h>
#include <cstdint>
#include <math.h>

// ---------------- problem constants ----------------
#define BB   4
#define NQ   8000
#define CC   256
#define NHD  8
#define NLV  4
#define NPT  4
#define DH   32
#define S_TOT 19947

#define MV (BB * S_TOT)   // 79788
#define MQ (BB * NQ)      // 32000

// ---------------- scratch ----------------
__device__ float g_value[(size_t)MV * CC];
__device__ float g_qout [(size_t)MQ * 384];
__device__ __nv_bfloat16 g_v_hi [(size_t)MV * CC];
__device__ __nv_bfloat16 g_v_lo [(size_t)MV * CC];
__device__ __nv_bfloat16 g_q_hi [(size_t)MQ * CC];
__device__ __nv_bfloat16 g_q_lo [(size_t)MQ * CC];
__device__ __nv_bfloat16 g_s_hi [(size_t)MQ * CC];
__device__ __nv_bfloat16 g_s_lo [(size_t)MQ * CC];
__device__ __nv_bfloat16 g_w_hi [65536 + 98304 + 65536];
__device__ __nv_bfloat16 g_w_lo [65536 + 98304 + 65536];
__device__ float g_qb[384];

// ---------------- helpers ----------------
__device__ __forceinline__ uint32_t smem_u32(const void* p) {
    uint32_t a;
    asm("{ .reg .u64 t; cvta.to.shared.u64 t, %1; cvt.u32.u64 %0, t; }" : "=r"(a) : "l"(p));
    return a;
}
__device__ __forceinline__ void ldsm4(uint32_t* r, uint32_t addr) {
    asm volatile("ldmatrix.sync.aligned.m8n8.x4.shared.b16 {%0,%1,%2,%3}, [%4];"
        : "=r"(r[0]), "=r"(r[1]), "=r"(r[2]), "=r"(r[3]) : "r"(addr));
}
__device__ __forceinline__ void mma_bf16(float* c, const uint32_t* a, const uint32_t* b) {
    asm volatile(
        "mma.sync.aligned.m16n8k16.row.col.f32.bf16.bf16.f32 "
        "{%0,%1,%2,%3}, {%4,%5,%6,%7}, {%8,%9}, {%0,%1,%2,%3};"
        : "+f"(c[0]), "+f"(c[1]), "+f"(c[2]), "+f"(c[3])
        : "r"(a[0]), "r"(a[1]), "r"(a[2]), "r"(a[3]), "r"(b[0]), "r"(b[1]));
}
__device__ __forceinline__ void cp_async16(uint32_t dst, const void* src, uint32_t sz) {
    asm volatile("cp.async.cg.shared.global [%0], [%1], 16, %2;"
        :: "r"(dst), "l"(src), "r"(sz) : "memory");
}
#define CP_COMMIT() asm volatile("cp.async.commit_group;" ::: "memory")
#define CP_WAIT(n)  asm volatile("cp.async.wait_group %0;" :: "n"(n) : "memory")

// ---------------- mega conversion kernel -------------------------------
#define NB_V  (MV / 4)
#define NB_Q  (MQ / 4)
#define NB_WV 64
#define NB_WO 64
#define NB_WA 32
#define NB_WU 64
#define NB_TOT (NB_V + NB_Q + NB_WV + NB_WO + NB_WA + NB_WU + 1)

struct ConvArgs {
    const float *vlv, *query, *w_val, *w_off, *w_attn, *w_out, *b_off, *b_attn;
};

__global__ void __launch_bounds__(256) convert_all_kernel(ConvArgs a)
{
    const int blk = blockIdx.x;
    const int tid = threadIdx.x;

    const float* src;
    uint2 *hi, *lo;
    int rel;

    if (blk < NB_V) {
        src = a.vlv; hi = (uint2*)g_v_hi; lo = (uint2*)g_v_lo; rel = blk;
    } else if (blk < NB_V + NB_Q) {
        src = a.query; hi = (uint2*)g_q_hi; lo = (uint2*)g_q_lo; rel = blk - NB_V;
    } else if (blk < NB_V + NB_Q + NB_WV) {
        src = a.w_val; hi = (uint2*)g_w_hi; lo = (uint2*)g_w_lo; rel = blk - (NB_V + NB_Q);
    } else if (blk < NB_V + NB_Q + NB_WV + NB_WO) {
        src = a.w_off; hi = (uint2*)(g_w_hi + 65536); lo = (uint2*)(g_w_lo + 65536);
        rel = blk - (NB_V + NB_Q + NB_WV);
    } else if (blk < NB_V + NB_Q + NB_WV + NB_WO + NB_WA) {
        src = a.w_attn; hi = (uint2*)(g_w_hi + 131072); lo = (uint2*)(g_w_lo + 131072);
        rel = blk - (NB_V + NB_Q + NB_WV + NB_WO);
    } else if (blk < NB_V + NB_Q + NB_WV + NB_WO + NB_WA + NB_WU) {
        src = a.w_out; hi = (uint2*)(g_w_hi + 163840); lo = (uint2*)(g_w_lo + 163840);
        rel = blk - (NB_V + NB_Q + NB_WV + NB_WO + NB_WA);
    } else {
        for (int i = tid; i < 384; i += 256)
            g_qb[i] = (i < 256) ? a.b_off[i] : a.b_attn[i - 256];
        return;
    }

    const int i = rel * 256 + tid;
    const float4 v = ((const float4*)src)[i];
    __nv_bfloat16 h0 = __float2bfloat16(v.x), h1 = __float2bfloat16(v.y);
    __nv_bfloat16 h2 = __float2bfloat16(v.z), h3 = __float2bfloat16(v.w);
    __nv_bfloat16 l0 = __float2bfloat16(v.x - __bfloat162float(h0));
    __nv_bfloat16 l1 = __float2bfloat16(v.y - __bfloat162float(h1));
    __nv_bfloat16 l2 = __float2bfloat16(v.z - __bfloat162float(h2));
    __nv_bfloat16 l3 = __float2bfloat16(v.w - __bfloat162float(h3));
    uint2 hp, lp;
    hp.x = (uint32_t)__bfloat16_as_ushort(h0) | ((uint32_t)__bfloat16_as_ushort(h1) << 16);
    hp.y = (uint32_t)__bfloat16_as_ushort(h2) | ((uint32_t)__bfloat16_as_ushort(h3) << 16);
    lp.x = (uint32_t)__bfloat16_as_ushort(l0) | ((uint32_t)__bfloat16_as_ushort(l1) << 16);
    lp.y = (uint32_t)__bfloat16_as_ushort(l2) | ((uint32_t)__bfloat16_as_ushort(l3) << 16);
    hi[i] = hp; lo[i] = lp;
}

// ============ HMMA GEMM: 128 threads/CTA, warp tile 64x64, 2 CTAs/SM ============
// tile 128x128, K staged in 8 half-stages of 32. smem 64KB: Ahi|Alo|Bhi|Blo 16KB planes.
struct GemmSeg {
    const __nv_bfloat16 *Ahi, *Alo, *Bhi, *Blo;
    const float* bias;
    float* C;
    int M, N, ntiles, tilesPerRow;
};

__global__ void __launch_bounds__(128, 2) gemm_tc2_kernel(GemmSeg s0, GemmSeg s1)
{
    extern __shared__ char smraw[];
    char* sm = (char*)(((uintptr_t)smraw + 1023) & ~(uintptr_t)1023);
    const uint32_t su = smem_u32(sm);
    float* pbias = (float*)(sm + 65536);

    int t = blockIdx.x;
    const __nv_bfloat16 *Ahi, *Alo, *Bhi, *Blo;
    const float* bias;
    float* Cmat;
    int M, N, tpr;
    if (t < s0.ntiles) {
        Ahi = s0.Ahi; Alo = s0.Alo; Bhi = s0.Bhi; Blo = s0.Blo;
        bias = s0.bias; Cmat = s0.C; M = s0.M; N = s0.N; tpr = s0.tilesPerRow;
    } else {
        t -= s0.ntiles;
        Ahi = s1.Ahi; Alo = s1.Alo; Bhi = s1.Bhi; Blo = s1.Blo;
        bias = s1.bias; Cmat = s1.C; M = s1.M; N = s1.N; tpr = s1.tilesPerRow;
    }
    const int bm = (t / tpr) * 128;
    const int bn = (t % tpr) * 128;

    const int tid  = threadIdx.x;
    const int lane = tid & 31;
    const int warp = tid >> 5;            // 0..3
    const int wm = (warp >> 1) * 64;      // 2x2 warp layout
    const int wn = (warp & 1) * 64;

    pbias[tid] = bias[bn + tid];          // 128 threads cover 128 cols

    float acc[4][8][4];
#pragma unroll
    for (int i = 0; i < 4; i++)
#pragma unroll
        for (int j = 0; j < 8; j++)
#pragma unroll
            for (int k = 0; k < 4; k++) acc[i][j][k] = 0.f;

    const uint32_t mx = (uint32_t)((lane & 7) << 4);
    uint32_t aRow[4], bRow[4];
#pragma unroll
    for (int mi = 0; mi < 4; mi++)
        aRow[mi] = (uint32_t)((wm + mi * 16 + (lane & 15)) * 128);
    const uint32_t colA = (uint32_t)((lane >> 4) * 16);
#pragma unroll
    for (int nj2 = 0; nj2 < 4; nj2++)
        bRow[nj2] = (uint32_t)((wn + nj2 * 16 + (lane & 7) + ((lane >> 4) & 1) * 8) * 128);
    const uint32_t colB = (uint32_t)(((lane >> 3) & 1) * 16);

    // one K-32 half-stage (hs) into half (hs&1) of all 4 planes. 128 threads.
    auto load_half = [&](int hs) {
        const int hb = (hs & 1) * 64;
        const int ksrc = hs * 64;
#pragma unroll
        for (int pl = 0; pl < 4; pl++) {
            const __nv_bfloat16* gsrc = (pl == 0) ? Ahi : (pl == 1) ? Alo : (pl == 2) ? Bhi : Blo;
            const bool isA = (pl < 2);
            const uint32_t pbase = su + (uint32_t)pl * 16384u;
#pragma unroll
            for (int it = 0; it < 4; it++) {
                const int idx = it * 128 + tid;        // 0..511
                const int r = idx >> 2;
                const int c = idx & 3;
                const uint32_t doff = (uint32_t)(r * 128)
                    + (uint32_t)((hb + c * 16) ^ ((r & 7) << 4));
                const int grow = (isA ? bm : bn) + r;
                const uint32_t sz = (isA && grow >= M) ? 0u : 16u;
                const size_t soff = (size_t)grow * 512 + ksrc + c * 16;
                cp_async16(pbase + doff, (const char*)gsrc + soff, sz);
            }
        }
    };

    load_half(0); CP_COMMIT();
    load_half(1); CP_COMMIT();

    for (int hs = 0; hs < 8; hs++) {
        if (hs < 7) CP_WAIT(1); else CP_WAIT(0);
        __syncthreads();

        const uint32_t hb = (uint32_t)((hs & 1) * 64);
#pragma unroll
        for (int kk = 0; kk < 2; kk++) {
            uint32_t ah[4][4], al[4][4], bh[4][4], bl[4][4];
            const uint32_t ca = (hb + (uint32_t)(kk * 32) + colA) ^ mx;
            const uint32_t cb = (hb + (uint32_t)(kk * 32) + colB) ^ mx;
#pragma unroll
            for (int mi = 0; mi < 4; mi++) {
                const uint32_t ad = su + aRow[mi] + ca;
                ldsm4(ah[mi], ad);
                ldsm4(al[mi], ad + 16384);
            }
#pragma unroll
            for (int nj2 = 0; nj2 < 4; nj2++) {
                const uint32_t bd = su + 32768 + bRow[nj2] + cb;
                ldsm4(bh[nj2], bd);
                ldsm4(bl[nj2], bd + 16384);
            }
#pragma unroll
            for (int mi = 0; mi < 4; mi++)
#pragma unroll
                for (int nj = 0; nj < 8; nj++)
                    mma_bf16(acc[mi][nj], ah[mi], &bh[nj >> 1][(nj & 1) * 2]);
#pragma unroll
            for (int mi = 0; mi < 4; mi++)
#pragma unroll
                for (int nj = 0; nj < 8; nj++)
                    mma_bf16(acc[mi][nj], ah[mi], &bl[nj >> 1][(nj & 1) * 2]);
#pragma unroll
            for (int mi = 0; mi < 4; mi++)
#pragma unroll
                for (int nj = 0; nj < 8; nj++)
                    mma_bf16(acc[mi][nj], al[mi], &bh[nj >> 1][(nj & 1) * 2]);
        }
        __syncthreads();
        if (hs < 6) { load_half(hs + 2); CP_COMMIT(); }
    }

    const int r0 = lane >> 2;
    const int c0 = (lane & 3) * 2;
#pragma unroll
    for (int mi = 0; mi < 4; mi++) {
        const int gm = bm + wm + mi * 16 + r0;
#pragma unroll
        for (int half = 0; half < 2; half++) {
            const int gmr = gm + half * 8;
            if (gmr < M) {
                float* op = Cmat + (size_t)gmr * N + bn;
#pragma unroll
                for (int nj = 0; nj < 8; nj++) {
                    const int cl = wn + nj * 8 + c0;
                    float2 o;
                    o.x = acc[mi][nj][half * 2 + 0] + pbias[cl];
                    o.y = acc[mi][nj][half * 2 + 1] + pbias[cl + 1];
                    *(float2*)(op + cl) = o;
                }
            }
        }
    }
}

// ---------------- sampling: softmax + quad-channel bilinear gather -------
__global__ void __launch_bounds__(256) sample_kernel(
    const float* __restrict__ ref)
{
    constexpr int LH[4]  = {100, 50, 25, 13};
    constexpr int LW[4]  = {150, 75, 38, 19};
    constexpr int LST[4] = {0, 15000, 18750, 19700};

    const int warp = (blockIdx.x * blockDim.x + threadIdx.x) >> 5;
    const int lane = threadIdx.x & 31;
    if (warp >= BB * NQ * NHD) return;

    const int h  = warp % NHD;
    const int bq = warp / NHD;
    const int b  = bq / NQ;
    const int sl = (lane >> 2) & 3;

    const float* qrow = g_qout + (size_t)bq * 384;

    const float* logit = qrow + 256 + h * 16;
    float lg = (lane < 16) ? logit[lane] : -1e30f;
    float mxv = lg;
#pragma unroll
    for (int o = 8; o; o >>= 1) mxv = fmaxf(mxv, __shfl_xor_sync(0xffffffffu, mxv, o, 16));
    float ev = __expf(lg - mxv);
    float sum = ev;
#pragma unroll
    for (int o = 8; o; o >>= 1) sum += __shfl_xor_sync(0xffffffffu, sum, o, 16);
    const float aw = ev / sum;

    const float2 off2 = ((const float2*)(qrow + h * 32))[lane & 15];
    const float2 rxy  = ((const float2*)(ref + (size_t)bq * 8))[sl];
    const float fW = (float)LW[sl], fH = (float)LH[sl];
    const float x = (rxy.x + off2.x / fW) * fW - 0.5f;
    const float y = (rxy.y + off2.y / fH) * fH - 0.5f;
    const float x0f = floorf(x), y0f = floorf(y);
    const float wx1 = x - x0f, wy1 = y - y0f;
    const int pk = (((int)y0f) << 16) | (((int)x0f) & 0xffff);
    const float wy0a_o = (1.f - wy1) * aw;
    const float wy1a_o = wy1 * aw;

    const int grp  = lane >> 3;
    const int chan = (lane & 7) * 4;
    float a0 = 0.f, a1 = 0.f, a2 = 0.f, a3 = 0.f;

#pragma unroll
    for (int l = 0; l < 4; l++) {
        const int W = LW[l], H = LH[l];
        const float* vbase = g_value
            + ((size_t)(b * S_TOT + LST[l]) * NHD + h) * DH + chan;
        const int src = l * 4 + grp;
        const int   bpk  = __shfl_sync(0xffffffffu, pk,     src);
        const float bwx  = __shfl_sync(0xffffffffu, wx1,    src);
        const float wy0a = __shfl_sync(0xffffffffu, wy0a_o, src);
        const float wy1a = __shfl_sync(0xffffffffu, wy1a_o, src);
        const int bix = (int)(short)(bpk & 0xffff);
        const int biy = bpk >> 16;
        const float wx0 = 1.f - bwx;
        const bool xi0 = (unsigned)bix < (unsigned)W;
        const bool xi1 = (unsigned)(bix + 1) < (unsigned)W;
        const bool yi0 = (unsigned)biy < (unsigned)H;
        const bool yi1 = (unsigned)(biy + 1) < (unsigned)H;
        const float* pp0 = vbase + (ptrdiff_t)(biy * W + bix) * 256;
        if (yi0 && xi0) { const float4 v = *(const float4*)pp0;
            const float w = wx0 * wy0a;
            a0 = fmaf(w, v.x, a0); a1 = fmaf(w, v.y, a1);
            a2 = fmaf(w, v.z, a2); a3 = fmaf(w, v.w, a3); }
        if (yi0 && xi1) { const float4 v = *(const float4*)(pp0 + 256);
            const float w = bwx * wy0a;
            a0 = fmaf(w, v.x, a0); a1 = fmaf(w, v.y, a1);
            a2 = fmaf(w, v.z, a2); a3 = fmaf(w, v.w, a3); }
        if (yi1 && xi0) { const float4 v = *(const float4*)(pp0 + W * 256);
            const float w = wx0 * wy1a;
            a0 = fmaf(w, v.x, a0); a1 = fmaf(w, v.y, a1);
            a2 = fmaf(w, v.z, a2); a3 = fmaf(w, v.w, a3); }
        if (yi1 && xi1) { const float4 v = *(const float4*)(pp0 + W * 256 + 256);
            const float w = bwx * wy1a;
            a0 = fmaf(w, v.x, a0); a1 = fmaf(w, v.y, a1);
            a2 = fmaf(w, v.z, a2); a3 = fmaf(w, v.w, a3); }
    }
#pragma unroll
    for (int o = 8; o <= 16; o <<= 1) {
        a0 += __shfl_xor_sync(0xffffffffu, a0, o);
        a1 += __shfl_xor_sync(0xffffffffu, a1, o);
        a2 += __shfl_xor_sync(0xffffffffu, a2, o);
        a3 += __shfl_xor_sync(0xffffffffu, a3, o);
    }

    if (lane < 8) {
        __nv_bfloat16 h0 = __float2bfloat16(a0), h1 = __float2bfloat16(a1);
        __nv_bfloat16 h2 = __float2bfloat16(a2), h3 = __float2bfloat16(a3);
        __nv_bfloat16 l0 = __float2bfloat16(a0 - __bfloat162float(h0));
        __nv_bfloat16 l1 = __float2bfloat16(a1 - __bfloat162float(h1));
        __nv_bfloat16 l2 = __float2bfloat16(a2 - __bfloat162float(h2));
        __nv_bfloat16 l3 = __float2bfloat16(a3 - __bfloat162float(h3));
        uint2 hp, lp;
        hp.x = (uint32_t)__bfloat16_as_ushort(h0) | ((uint32_t)__bfloat16_as_ushort(h1) << 16);
        hp.y = (uint32_t)__bfloat16_as_ushort(h2) | ((uint32_t)__bfloat16_as_ushort(h3) << 16);
        lp.x = (uint32_t)__bfloat16_as_ushort(l0) | ((uint32_t)__bfloat16_as_ushort(l1) << 16);
        lp.y = (uint32_t)__bfloat16_as_ushort(l2) | ((uint32_t)__bfloat16_as_ushort(l3) << 16);
        const size_t q2 = (size_t)(bq * NHD + h) * 8 + (lane & 7);
        ((uint2*)g_s_hi)[q2] = hp;
        ((uint2*)g_s_lo)[q2] = lp;
    }
}

// ---------------- launch ----------------
#define GEMM_SMEM_BYTES 67584

extern "C" void kernel_launch(void* const* d_in, const int* in_sizes, int n_in,
                              void* d_out, int out_size)
{
    (void)in_sizes; (void)n_in; (void)out_size;
    const float* query  = (const float*)d_in[0];
    const float* vlv    = (const float*)d_in[1];
    const float* refpts = (const float*)d_in[2];
    const float* W_off  = (const float*)d_in[4];
    const float* b_off  = (const float*)d_in[5];
    const float* W_attn = (const float*)d_in[6];
    const float* b_attn = (const float*)d_in[7];
    const float* W_val  = (const float*)d_in[8];
    const float* b_val  = (const float*)d_in[9];
    const float* W_out  = (const float*)d_in[10];
    const float* b_out  = (const float*)d_in[11];
    float* out = (float*)d_out;

    cudaFuncSetAttribute(gemm_tc2_kernel,
                         cudaFuncAttributeMaxDynamicSharedMemorySize, GEMM_SMEM_BYTES);

    float *p_value, *p_qout, *p_qb;
    __nv_bfloat16 *p_vhi, *p_vlo, *p_qhi, *p_qlo, *p_shi, *p_slo, *p_whi, *p_wlo;
    cudaGetSymbolAddress((void**)&p_value, g_value);
    cudaGetSymbolAddress((void**)&p_qout,  g_qout);
    cudaGetSymbolAddress((void**)&p_qb,    g_qb);
    cudaGetSymbolAddress((void**)&p_vhi,   g_v_hi);
    cudaGetSymbolAddress((void**)&p_vlo,   g_v_lo);
    cudaGetSymbolAddress((void**)&p_qhi,   g_q_hi);
    cudaGetSymbolAddress((void**)&p_qlo,   g_q_lo);
    cudaGetSymbolAddress((void**)&p_shi,   g_s_hi);
    cudaGetSymbolAddress((void**)&p_slo,   g_s_lo);
    cudaGetSymbolAddress((void**)&p_whi,   g_w_hi);
    cudaGetSymbolAddress((void**)&p_wlo,   g_w_lo);

    __nv_bfloat16 *wv_hi = p_whi,           *wv_lo = p_wlo;
    __nv_bfloat16 *qw_hi = p_whi + 65536,   *qw_lo = p_wlo + 65536;
    __nv_bfloat16 *wu_hi = p_whi + 163840,  *wu_lo = p_wlo + 163840;

    {
        ConvArgs ca;
        ca.vlv = vlv; ca.query = query;
        ca.w_val = W_val; ca.w_off = W_off; ca.w_attn = W_attn; ca.w_out = W_out;
        ca.b_off = b_off; ca.b_attn = b_attn;
        convert_all_kernel<<<NB_TOT, 256>>>(ca);
    }

    {
        GemmSeg sv, sq;
        sv.Ahi = p_vhi; sv.Alo = p_vlo; sv.Bhi = wv_hi; sv.Blo = wv_lo;
        sv.bias = b_val; sv.C = p_value; sv.M = MV; sv.N = 256;
        sv.tilesPerRow = 2; sv.ntiles = ((MV + 127) / 128) * 2;
        sq.Ahi = p_qhi; sq.Alo = p_qlo; sq.Bhi = qw_hi; sq.Blo = qw_lo;
        sq.bias = p_qb; sq.C = p_qout; sq.M = MQ; sq.N = 384;
        sq.tilesPerRow = 3; sq.ntiles = (MQ / 128) * 3;
        gemm_tc2_kernel<<<sv.ntiles + sq.ntiles, 128, GEMM_SMEM_BYTES>>>(sv, sq);
    }

    {
        const int nwarp = BB * NQ * NHD;
        sample_kernel<<<(nwarp * 32 + 255) / 256, 256>>>(refpts);
    }

    {
        GemmSeg so, dummy;
        so.Ahi = p_shi; so.Alo = p_slo; so.Bhi = wu_hi; so.Blo = wu_lo;
        so.bias = b_out; so.C = out; so.M = MQ; so.N = 256;
        so.tilesPerRow = 2; so.ntiles = (MQ / 128) * 2;
        dummy = so; dummy.ntiles = 0;
        gemm_tc2_kernel<<<so.ntiles, 128, GEMM_SMEM_BYTES>>>(so, dummy);
    }
}